// round 7
// baseline (speedup 1.0000x reference)
#include <cuda_runtime.h>
#include <math.h>

// Problem dims
#define NB 2
#define NN 512
#define CSD 384
#define NH 12
#define NC 16
#define NP 8
#define NPV 8
#define NK 16
#define NG 64
#define HC (NH*NC)          // 192
#define HPV3 (NH*NPV*3)     // 288

// ---------------- scratch (device globals) -------------
__device__ __align__(16) float g_q   [NB*NN*HC];
__device__ __align__(16) float g_k   [NB*NN*HC];
__device__ __align__(16) float g_v   [NB*NN*HC];
__device__ __align__(16) float g_qpts[NB*NN*NP*3];
__device__ __align__(16) float g_vpts[NB*NN*NP*3];
__device__ __align__(16) float g_vg  [NB*NN*HPV3];
__device__ __align__(16) float g_logits[(size_t)NB*NH*NN*NN];
__device__ __align__(16) float g_o   [NB*NN*HC];
__device__ __align__(16) float g_opt [NB*NN*HPV3];

// ================= K1: per-row projections, 8 rows per block =================
#define K1R 8
__global__ void k1_project(const float* __restrict__ s,
                           const float* __restrict__ rot,
                           const float* __restrict__ trans,
                           const float* __restrict__ Wq,  const float* __restrict__ bq,
                           const float* __restrict__ Wkv, const float* __restrict__ bkv,
                           const float* __restrict__ ln_g,const float* __restrict__ ln_b,
                           const float* __restrict__ Wpq, const float* __restrict__ bpq,
                           const float* __restrict__ Wpv, const float* __restrict__ bpv,
                           const float* __restrict__ Wkvp,const float* __restrict__ bkvp)
{
    __shared__ float ssh [K1R*CSD];
    __shared__ float snsh[K1R*CSD];
    __shared__ float kvpsh[K1R*HPV3];

    int bn0 = blockIdx.x * K1R;
    int tid = threadIdx.x;
    int wid = tid >> 5, lane = tid & 31;

    for (int idx = tid; idx < K1R*CSD; idx += blockDim.x)
        ssh[idx] = s[(size_t)bn0 * CSD + idx];
    __syncthreads();

    {
        int r = wid;
        const float* row = ssh + r * CSD;
        float lsum = 0.f;
        for (int i = lane; i < CSD; i += 32) lsum += row[i];
        #pragma unroll
        for (int o = 16; o > 0; o >>= 1) lsum += __shfl_xor_sync(0xffffffffu, lsum, o);
        float mean = lsum * (1.0f / CSD);
        float lvar = 0.f;
        for (int i = lane; i < CSD; i += 32) { float d = row[i] - mean; lvar += d * d; }
        #pragma unroll
        for (int o = 16; o > 0; o >>= 1) lvar += __shfl_xor_sync(0xffffffffu, lvar, o);
        float inv = rsqrtf(lvar * (1.0f / CSD) + 1e-5f);
        for (int i = lane; i < CSD; i += 32)
            snsh[r * CSD + i] = (row[i] - mean) * inv * ln_g[i] + ln_b[i];
    }
    __syncthreads();

    for (int col = tid; col < 912; col += blockDim.x) {
        float acc[K1R];
        if (col < HC) {
            #pragma unroll
            for (int r = 0; r < K1R; r++) acc[r] = bq[col];
            for (int cs = 0; cs < CSD; cs++) {
                float w = Wq[(size_t)cs * HC + col];
                #pragma unroll
                for (int r = 0; r < K1R; r++) acc[r] += ssh[r*CSD+cs] * w;
            }
            #pragma unroll
            for (int r = 0; r < K1R; r++) g_q[(size_t)(bn0+r) * HC + col] = acc[r];
        } else if (col < 3*HC) {
            int j2 = col - HC;
            #pragma unroll
            for (int r = 0; r < K1R; r++) acc[r] = bkv[j2];
            for (int cs = 0; cs < CSD; cs++) {
                float w = Wkv[(size_t)cs * (2*HC) + j2];
                #pragma unroll
                for (int r = 0; r < K1R; r++) acc[r] += ssh[r*CSD+cs] * w;
            }
            int h = j2 >> 5, rr = j2 & 31;
            #pragma unroll
            for (int r = 0; r < K1R; r++) {
                if (rr < NC) g_k[(size_t)(bn0+r) * HC + h * NC + rr] = acc[r];
                else         g_v[(size_t)(bn0+r) * HC + h * NC + (rr - NC)] = acc[r];
            }
        } else if (col < 600) {
            int c2 = col - 576;
            #pragma unroll
            for (int r = 0; r < K1R; r++) acc[r] = bpq[c2];
            for (int cs = 0; cs < CSD; cs++) {
                float w = Wpq[(size_t)cs * (NP*3) + c2];
                #pragma unroll
                for (int r = 0; r < K1R; r++) acc[r] += snsh[r*CSD+cs] * w;
            }
            #pragma unroll
            for (int r = 0; r < K1R; r++) g_qpts[(size_t)(bn0+r) * (NP*3) + c2] = acc[r];
        } else if (col < 624) {
            int c2 = col - 600;
            #pragma unroll
            for (int r = 0; r < K1R; r++) acc[r] = bpv[c2];
            for (int cs = 0; cs < CSD; cs++) {
                float w = Wpv[(size_t)cs * (NP*3) + c2];
                #pragma unroll
                for (int r = 0; r < K1R; r++) acc[r] += snsh[r*CSD+cs] * w;
            }
            #pragma unroll
            for (int r = 0; r < K1R; r++) g_vpts[(size_t)(bn0+r) * (NP*3) + c2] = acc[r];
        } else {
            int c2 = col - 624;
            #pragma unroll
            for (int r = 0; r < K1R; r++) acc[r] = bkvp[c2];
            for (int cs = 0; cs < CSD; cs++) {
                float w = Wkvp[(size_t)cs * HPV3 + c2];
                #pragma unroll
                for (int r = 0; r < K1R; r++) acc[r] += ssh[r*CSD+cs] * w;
            }
            #pragma unroll
            for (int r = 0; r < K1R; r++) kvpsh[r*HPV3 + c2] = acc[r];
        }
    }
    __syncthreads();

    for (int t = tid; t < K1R*HPV3; t += blockDim.x) {
        int r = t / HPV3, e = t - r*HPV3;
        int kidx = e / 3, x = e % 3;
        int bn = bn0 + r;
        const float* rp = rot + (size_t)bn * 9;
        const float* tp = trans + (size_t)bn * 3;
        float vv = tp[x] * 0.1f;
        #pragma unroll
        for (int y = 0; y < 3; y++) vv += rp[x * 3 + y] * kvpsh[r*HPV3 + kidx * 3 + y];
        g_vg[(size_t)bn * HPV3 + e] = vv;
    }
}

// ================= K2: pair stage (j-tiled GEMM, JT=32, 2 blocks/SM) ==========
// shared layout (floats)
#define OFF_WG    0          // [128][64] 8192
#define OFF_W1    8192       // [64][64]  4096 -> 12288
#define OFF_W2    12288      // [64][12]  768  -> 13056
#define OFF_WVL   13056      // 128 -> 13184
#define OFF_MEAN  13184
#define OFF_ISTD  13200
#define OFF_BG    13216
#define OFF_B1    13280
#define OFF_B2    13344
#define OFF_HW    13360
#define OFF_ROTI  13376
#define OFF_TI    13388
#define OFF_MASKI 13391
#define OFF_QPTS  13392
#define OFF_QVL   13416
#define OFF_QI    13440      // 192 -> 13632
#define OFF_VLOC  13632      // [32][25] -> 14432
#define OFF_VLEN  14432      // [32][8]  -> 14688
#define OFF_GAU   14688      // [32][132]-> 18912 (reused for h1)
#define OFF_GB    18912      // [32][68] -> 21088
#define OFF_LG    21088      // [12][33] -> 21484
#define SMEM2_FLOATS 21484
#define SMEM2_BYTES  (SMEM2_FLOATS * 4)
#define JT 32

__global__ void k2_pair(const float* __restrict__ rot,
                        const float* __restrict__ trans,
                        const float* __restrict__ mask,
                        const float* __restrict__ head_weights,
                        const float* __restrict__ Wvl,
                        const float* __restrict__ gbf_means,
                        const float* __restrict__ gbf_stds,
                        const float* __restrict__ Wg, const float* __restrict__ bg,
                        const float* __restrict__ W1, const float* __restrict__ b1,
                        const float* __restrict__ W2, const float* __restrict__ b2,
                        float* __restrict__ g_out)
{
    extern __shared__ float sh[];
    int bi = blockIdx.x;
    int b = bi >> 9, i = bi & 511;
    int tid = threadIdx.x;

    for (int t = tid; t < 8192; t += 256) sh[OFF_WG + t] = Wg[t];
    for (int t = tid; t < 4096; t += 256) sh[OFF_W1 + t] = W1[t];
    for (int t = tid; t < 768;  t += 256) sh[OFF_W2 + t] = W2[t];
    if (tid < 128) sh[OFF_WVL + tid] = Wvl[tid];
    if (tid < NK) {
        sh[OFF_MEAN + tid] = gbf_means[tid];
        sh[OFF_ISTD + tid] = 1.0f / gbf_stds[tid];
    }
    if (tid < NG) { sh[OFF_BG + tid] = bg[tid]; sh[OFF_B1 + tid] = b1[tid]; }
    if (tid < NH) {
        sh[OFF_B2 + tid] = b2[tid];
        float x = head_weights[tid];
        float sp = logf(1.0f + expf(x));
        sh[OFF_HW + tid] = sp * (-0.11785113f);   // softplus * sqrt(1/18) * -0.5
    }
    if (tid < 9) sh[OFF_ROTI + tid] = rot[(size_t)bi * 9 + tid];
    if (tid < 3) sh[OFF_TI + tid] = trans[(size_t)bi * 3 + tid];
    if (tid < 24) sh[OFF_QPTS + tid] = g_qpts[(size_t)bi * 24 + tid];
    if (tid == 0) sh[OFF_MASKI] = mask[bi];
    if (tid < HC) sh[OFF_QI + tid] = g_q[(size_t)bi * HC + tid];
    __syncthreads();

    if (tid < 24) {  // q-contribution of Wvl (j-independent)
        int o = tid / 3, x = tid % 3;
        float acc = 0.f;
        #pragma unroll
        for (int p = 0; p < NP; p++)
            acc += sh[OFF_WVL + o * 16 + 8 + p] * sh[OFF_QPTS + p * 3 + x];
        sh[OFF_QVL + tid] = acc;
    }
    __syncthreads();

    float ti0 = sh[OFF_TI + 0], ti1 = sh[OFF_TI + 1], ti2 = sh[OFF_TI + 2];
    float mi = sh[OFF_MASKI];
    int ty = tid >> 4, tx = tid & 15;

    const float4* WG4 = (const float4*)(sh + OFF_WG);
    const float4* W14 = (const float4*)(sh + OFF_W1);

    for (int j0 = 0; j0 < NN; j0 += JT) {
        // ---- A: v_loc, 8 threads per j (one p each) ----
        {
            int jj = tid >> 3, p = tid & 7;
            int j = j0 + jj;
            const float* rj = rot + ((size_t)b * NN + j) * 9;
            const float* tj = trans + ((size_t)b * NN + j) * 3;
            float R[3][3], tr[3];
            #pragma unroll
            for (int x = 0; x < 3; x++) {
                float a0 = sh[OFF_ROTI + 0*3 + x];
                float a1 = sh[OFF_ROTI + 1*3 + x];
                float a2 = sh[OFF_ROTI + 2*3 + x];
                #pragma unroll
                for (int z = 0; z < 3; z++)
                    R[x][z] = a0 * rj[0*3+z] + a1 * rj[1*3+z] + a2 * rj[2*3+z];
                tr[x] = a0 * (tj[0] - ti0) + a1 * (tj[1] - ti1) + a2 * (tj[2] - ti2);
            }
            const float* vp = g_vpts + ((size_t)b * NN + j) * 24 + p * 3;
            float v0 = vp[0], v1 = vp[1], v2 = vp[2];
            #pragma unroll
            for (int x = 0; x < 3; x++)
                sh[OFF_VLOC + jj*25 + p*3 + x] = R[x][0]*v0 + R[x][1]*v1 + R[x][2]*v2 + tr[x];
        }
        __syncthreads();
        // ---- B: vec + vlen, one (jj,o) per thread ----
        {
            int jj = tid >> 3, o = tid & 7;
            const float* vl = sh + OFF_VLOC + jj*25;
            float vx = sh[OFF_QVL + o*3+0] + vl[o*3+0];
            float vy = sh[OFF_QVL + o*3+1] + vl[o*3+1];
            float vz = sh[OFF_QVL + o*3+2] + vl[o*3+2];
            #pragma unroll
            for (int p = 0; p < NP; p++) {
                float w_ = sh[OFF_WVL + o * 16 + p];
                vx += w_ * vl[p*3+0];
                vy += w_ * vl[p*3+1];
                vz += w_ * vl[p*3+2];
            }
            sh[OFF_VLEN + jj*8 + o] = sqrtf(vx*vx + vy*vy + vz*vz + 1e-8f);
        }
        __syncthreads();
        // ---- C: gauss [32][128] ----
        #pragma unroll
        for (int it = 0; it < 16; it++) {
            int flat = tid + 256 * it;
            int jj = flat >> 7, m = flat & 127;
            int p = m >> 4, kk = m & 15;
            float d = (sh[OFF_VLEN + jj*8 + p] - sh[OFF_MEAN + kk]) * sh[OFF_ISTD + kk];
            sh[OFF_GAU + jj*132 + m] = __expf(-0.5f * d * d);
        }
        __syncthreads();
        // ---- D: g[32][64] = gauss @ Wg + bg (2x4 register tile) ----
        {
            float acc[2][4];
            #pragma unroll
            for (int r = 0; r < 2; r++)
                #pragma unroll
                for (int c = 0; c < 4; c++) acc[r][c] = sh[OFF_BG + tx*4 + c];
            #pragma unroll 4
            for (int m = 0; m < 128; m++) {
                float4 wv = WG4[m * 16 + tx];
                float ga0 = sh[OFF_GAU + (2*ty+0)*132 + m];
                float ga1 = sh[OFF_GAU + (2*ty+1)*132 + m];
                acc[0][0] += ga0*wv.x; acc[0][1] += ga0*wv.y; acc[0][2] += ga0*wv.z; acc[0][3] += ga0*wv.w;
                acc[1][0] += ga1*wv.x; acc[1][1] += ga1*wv.y; acc[1][2] += ga1*wv.z; acc[1][3] += ga1*wv.w;
            }
            #pragma unroll
            for (int r = 0; r < 2; r++) {
                int jj = 2*ty + r;
                float4 v4 = make_float4(acc[r][0], acc[r][1], acc[r][2], acc[r][3]);
                *(float4*)(sh + OFF_GB + jj*68 + tx*4) = v4;
                *(float4*)(g_out + ((size_t)bi * NN + j0 + jj) * NG + tx*4) = v4;
            }
        }
        __syncthreads();
        // ---- E: h1[32][64] = relu(g @ W1 + b1), overwrite GAU ----
        {
            float acc[2][4];
            #pragma unroll
            for (int r = 0; r < 2; r++)
                #pragma unroll
                for (int c = 0; c < 4; c++) acc[r][c] = sh[OFF_B1 + tx*4 + c];
            #pragma unroll 4
            for (int m = 0; m < 64; m++) {
                float4 wv = W14[m * 16 + tx];
                float ga0 = sh[OFF_GB + (2*ty+0)*68 + m];
                float ga1 = sh[OFF_GB + (2*ty+1)*68 + m];
                acc[0][0] += ga0*wv.x; acc[0][1] += ga0*wv.y; acc[0][2] += ga0*wv.z; acc[0][3] += ga0*wv.w;
                acc[1][0] += ga1*wv.x; acc[1][1] += ga1*wv.y; acc[1][2] += ga1*wv.z; acc[1][3] += ga1*wv.w;
            }
            __syncthreads();   // gauss fully consumed; safe to overwrite GAU with h1
            #pragma unroll
            for (int r = 0; r < 2; r++) {
                int jj = 2*ty + r;
                *(float4*)(sh + OFF_GAU + jj*132 + tx*4) =
                    make_float4(fmaxf(acc[r][0],0.f), fmaxf(acc[r][1],0.f),
                                fmaxf(acc[r][2],0.f), fmaxf(acc[r][3],0.f));
            }
        }
        __syncthreads();
        // ---- F: vfn + qk + dist -> logits (staged in smem) ----
        for (int idx = tid; idx < JT * NH; idx += 256) {
            int jj = idx & 31, h = idx >> 5;
            int j = j0 + jj;
            float acc = sh[OFF_B2 + h];
            const float* h1 = sh + OFF_GAU + jj*132;
            #pragma unroll 8
            for (int m = 0; m < 64; m++)
                acc += h1[m] * sh[OFF_W2 + m * NH + h];
            const float4* kp = (const float4*)(g_k + ((size_t)b * NN + j) * HC + h * NC);
            const float4* qp = (const float4*)(sh + OFF_QI + h * NC);
            float qk = 0.f;
            #pragma unroll
            for (int c = 0; c < 4; c++) {
                float4 kk4 = kp[c], qq4 = qp[c];
                qk += qq4.x*kk4.x + qq4.y*kk4.y + qq4.z*kk4.z + qq4.w*kk4.w;
            }
            const float* tj = trans + ((size_t)b * NN + j) * 3;
            float d0 = (tj[0] - ti0) * 0.1f;
            float d1 = (tj[1] - ti1) * 0.1f;
            float d2 = (tj[2] - ti2) * 0.1f;
            float pd = d0*d0 + d1*d1 + d2*d2;
            float mj = mask[(size_t)b * NN + j];
            sh[OFF_LG + h*33 + jj] = qk * 0.125f + acc * 0.5f + pd * sh[OFF_HW + h]
                                   + 100000.0f * (mi * mj - 1.0f);
        }
        __syncthreads();
        // coalesced writeout: consecutive jj per h
        for (int idx = tid; idx < JT * NH; idx += 256) {
            int h = idx >> 5, jj = idx & 31;
            g_logits[((((size_t)b * NH + h) * NN) + i) * NN + j0 + jj] = sh[OFF_LG + h*33 + jj];
        }
        __syncthreads();
    }
}

// ================= K4: fused softmax + attention-weighted sums =================
#define K4_AST 520
#define K4_SMEM_FLOATS (32*K4_AST + 64*41)
#define K4_SMEM_BYTES  (K4_SMEM_FLOATS * 4)
__global__ void k4_attn()
{
    extern __shared__ float sh4[];
    float* a_sh = sh4;                 // [32][520]
    float* v_sh = sh4 + 32*K4_AST;     // [64][41]

    int blk = blockIdx.x;
    int it = blk & 15;
    int h  = (blk >> 4) % 12;
    int b  = blk / (16 * 12);
    int i0 = it * 32;
    int tid = threadIdx.x;

    const float* Arow = g_logits + (((size_t)b * NH + h) * NN + i0) * NN;

    for (int idx = tid; idx < 32*512; idx += 256) {
        int ii = idx >> 9, jj = idx & 511;
        a_sh[ii*K4_AST + jj] = Arow[(size_t)ii * NN + jj];
    }
    __syncthreads();

    {
        int r = tid >> 3, t8 = tid & 7;
        float* row = a_sh + r * K4_AST;
        float mx = -1e30f;
        for (int jj = t8; jj < 512; jj += 8) mx = fmaxf(mx, row[jj]);
        #pragma unroll
        for (int o = 4; o > 0; o >>= 1) mx = fmaxf(mx, __shfl_xor_sync(0xffffffffu, mx, o));
        float sm = 0.f;
        for (int jj = t8; jj < 512; jj += 8) {
            float e = __expf(row[jj] - mx);
            row[jj] = e;
            sm += e;
        }
        #pragma unroll
        for (int o = 4; o > 0; o >>= 1) sm += __shfl_xor_sync(0xffffffffu, sm, o);
        float inv = 1.0f / sm;
        for (int jj = t8; jj < 512; jj += 8) row[jj] *= inv;
    }
    __syncthreads();

    int q  = tid & 7;        // 5 cols each
    int ip = tid >> 3;       // i row
    float acc[5];
    #pragma unroll
    for (int c = 0; c < 5; c++) acc[c] = 0.f;

    for (int jt = 0; jt < NN; jt += 64) {
        for (int idx = tid; idx < 64*40; idx += 256) {
            int jj = idx / 40, c = idx - jj*40;
            int j = jt + jj;
            float v;
            if (c < 16) v = g_v [((size_t)b * NN + j) * HC   + h * NC + c];
            else        v = g_vg[((size_t)b * NN + j) * HPV3 + h * 24 + (c - 16)];
            v_sh[jj*41 + c] = v;
        }
        __syncthreads();
        const float* arow = a_sh + ip*K4_AST + jt;
        #pragma unroll 4
        for (int jj = 0; jj < 64; jj++) {
            float a0 = arow[jj];
            const float* vp = v_sh + jj*41 + q*5;
            #pragma unroll
            for (int c = 0; c < 5; c++) acc[c] += a0 * vp[c];
        }
        __syncthreads();
    }

    int ig = i0 + ip;
    #pragma unroll
    for (int c = 0; c < 5; c++) {
        int col = q*5 + c;
        if (col < 16) g_o  [((size_t)b * NN + ig) * HC   + h * NC + col]      = acc[c];
        else          g_opt[((size_t)b * NN + ig) * HPV3 + h * 24 + (col-16)] = acc[c];
    }
}

// ================= K5: final features + output GEMV, 4 rows/block =================
#define K5R 4
__global__ void k5_out(const float* __restrict__ rot,
                       const float* __restrict__ trans,
                       const float* __restrict__ Wout,
                       const float* __restrict__ bout,
                       float* __restrict__ sout)
{
    __shared__ float feats[K5R*576];
    int bi0 = blockIdx.x * K5R;
    int tid = threadIdx.x;

    for (int idx = tid; idx < K5R*HC; idx += 384) {
        int r = idx / HC, c = idx - r*HC;
        feats[r*576 + c] = g_o[(size_t)(bi0+r) * HC + c];
    }
    for (int idx = tid; idx < K5R*96; idx += 384) {
        int r = idx / 96, kidx = idx - r*96;
        int bi = bi0 + r;
        const float* rp = rot + (size_t)bi * 9;
        const float* tp = trans + (size_t)bi * 3;
        float oy0 = g_opt[(size_t)bi * HPV3 + kidx*3+0] - tp[0] * 0.1f;
        float oy1 = g_opt[(size_t)bi * HPV3 + kidx*3+1] - tp[1] * 0.1f;
        float oy2 = g_opt[(size_t)bi * HPV3 + kidx*3+2] - tp[2] * 0.1f;
        float l0 = rp[0]*oy0 + rp[3]*oy1 + rp[6]*oy2;
        float l1 = rp[1]*oy0 + rp[4]*oy1 + rp[7]*oy2;
        float l2 = rp[2]*oy0 + rp[5]*oy1 + rp[8]*oy2;
        feats[r*576 + 192 + kidx] = l0;
        feats[r*576 + 288 + kidx] = l1;
        feats[r*576 + 384 + kidx] = l2;
        feats[r*576 + 480 + kidx] = sqrtf(l0*l0 + l1*l1 + l2*l2 + 1e-8f);
    }
    __syncthreads();

    int cs = tid;  // blockDim = 384
    float acc[K5R];
    float bb = bout[cs];
    #pragma unroll
    for (int r = 0; r < K5R; r++) acc[r] = bb;
    for (int f0 = 0; f0 < 576; f0 += 8) {
        float w[8];
        #pragma unroll
        for (int u = 0; u < 8; u++) w[u] = Wout[(size_t)(f0+u) * CSD + cs];
        #pragma unroll
        for (int u = 0; u < 8; u++) {
            #pragma unroll
            for (int r = 0; r < K5R; r++) acc[r] += feats[r*576 + f0 + u] * w[u];
        }
    }
    #pragma unroll
    for (int r = 0; r < K5R; r++)
        sout[(size_t)(bi0+r) * CSD + cs] = acc[r];
}

// ================= launch =================
extern "C" void kernel_launch(void* const* d_in, const int* in_sizes, int n_in,
                              void* d_out, int out_size)
{
    const float* s        = (const float*)d_in[0];
    const float* rot      = (const float*)d_in[1];
    const float* trans    = (const float*)d_in[2];
    const float* mask     = (const float*)d_in[3];
    const float* Wq       = (const float*)d_in[4];
    const float* bq       = (const float*)d_in[5];
    const float* Wkv      = (const float*)d_in[6];
    const float* bkv      = (const float*)d_in[7];
    const float* head_w   = (const float*)d_in[8];
    const float* ln_g     = (const float*)d_in[9];
    const float* ln_b     = (const float*)d_in[10];
    const float* Wpq      = (const float*)d_in[11];
    const float* bpq      = (const float*)d_in[12];
    const float* Wpv      = (const float*)d_in[13];
    const float* bpv      = (const float*)d_in[14];
    const float* Wvl      = (const float*)d_in[15];
    const float* gbf_mean = (const float*)d_in[16];
    const float* gbf_std  = (const float*)d_in[17];
    const float* Wg       = (const float*)d_in[18];
    const float* bg       = (const float*)d_in[19];
    const float* W1       = (const float*)d_in[20];
    const float* b1       = (const float*)d_in[21];
    const float* W2       = (const float*)d_in[22];
    const float* b2       = (const float*)d_in[23];
    const float* Wkvp     = (const float*)d_in[24];
    const float* bkvp     = (const float*)d_in[25];
    const float* Wout     = (const float*)d_in[26];
    const float* bout     = (const float*)d_in[27];

    float* out = (float*)d_out;
    float* sout_part = out;                              // (B,N,CS)
    float* g_part = out + (size_t)NB * NN * CSD;         // (B,N,N,G)

    cudaFuncSetAttribute((const void*)k2_pair,
                         cudaFuncAttributeMaxDynamicSharedMemorySize, SMEM2_BYTES);
    cudaFuncSetAttribute((const void*)k4_attn,
                         cudaFuncAttributeMaxDynamicSharedMemorySize, K4_SMEM_BYTES);

    k1_project<<<NB * NN / K1R, 256>>>(s, rot, trans, Wq, bq, Wkv, bkv,
                                       ln_g, ln_b, Wpq, bpq, Wpv, bpv, Wkvp, bkvp);
    k2_pair<<<NB * NN, 256, SMEM2_BYTES>>>(rot, trans, mask, head_w, Wvl,
                                           gbf_mean, gbf_std, Wg, bg, W1, b1,
                                           W2, b2, g_part);
    k4_attn<<<NB * NH * (NN/32), 256, K4_SMEM_BYTES>>>();
    k5_out<<<NB * NN / K5R, 384>>>(rot, trans, Wout, bout, sout_part);
}

// round 9
// speedup vs baseline: 1.1756x; 1.1756x over previous
#include <cuda_runtime.h>
#include <math.h>

// Problem dims
#define NB 2
#define NN 512
#define CSD 384
#define NH 12
#define NC 16
#define NP 8
#define NPV 8
#define NK 16
#define NG 64
#define HC (NH*NC)          // 192
#define HPV3 (NH*NPV*3)     // 288

// ---------------- scratch (device globals) -------------
__device__ __align__(16) float g_q   [NB*NN*HC];
__device__ __align__(16) float g_k   [NB*NN*HC];
__device__ __align__(16) float g_v   [NB*NN*HC];
__device__ __align__(16) float g_qpts[NB*NN*NP*3];
__device__ __align__(16) float g_vpts[NB*NN*NP*3];
__device__ __align__(16) float g_vg  [NB*NN*HPV3];
__device__ __align__(16) float g_probs[(size_t)NB*NH*NN*NN];
__device__ __align__(16) float g_o   [NB*NN*HC];
__device__ __align__(16) float g_opt [NB*NN*HPV3];

// ================= K1: per-row projections, 8 rows per block =================
#define K1R 8
__global__ void k1_project(const float* __restrict__ s,
                           const float* __restrict__ rot,
                           const float* __restrict__ trans,
                           const float* __restrict__ Wq,  const float* __restrict__ bq,
                           const float* __restrict__ Wkv, const float* __restrict__ bkv,
                           const float* __restrict__ ln_g,const float* __restrict__ ln_b,
                           const float* __restrict__ Wpq, const float* __restrict__ bpq,
                           const float* __restrict__ Wpv, const float* __restrict__ bpv,
                           const float* __restrict__ Wkvp,const float* __restrict__ bkvp)
{
    __shared__ float ssh [K1R*CSD];
    __shared__ float snsh[K1R*CSD];
    __shared__ float kvpsh[K1R*HPV3];

    int bn0 = blockIdx.x * K1R;
    int tid = threadIdx.x;
    int wid = tid >> 5, lane = tid & 31;

    for (int idx = tid; idx < K1R*CSD; idx += blockDim.x)
        ssh[idx] = s[(size_t)bn0 * CSD + idx];
    __syncthreads();

    {
        int r = wid;
        const float* row = ssh + r * CSD;
        float lsum = 0.f;
        for (int i = lane; i < CSD; i += 32) lsum += row[i];
        #pragma unroll
        for (int o = 16; o > 0; o >>= 1) lsum += __shfl_xor_sync(0xffffffffu, lsum, o);
        float mean = lsum * (1.0f / CSD);
        float lvar = 0.f;
        for (int i = lane; i < CSD; i += 32) { float d = row[i] - mean; lvar += d * d; }
        #pragma unroll
        for (int o = 16; o > 0; o >>= 1) lvar += __shfl_xor_sync(0xffffffffu, lvar, o);
        float inv = rsqrtf(lvar * (1.0f / CSD) + 1e-5f);
        for (int i = lane; i < CSD; i += 32)
            snsh[r * CSD + i] = (row[i] - mean) * inv * ln_g[i] + ln_b[i];
    }
    __syncthreads();

    for (int col = tid; col < 912; col += blockDim.x) {
        float acc[K1R];
        if (col < HC) {
            #pragma unroll
            for (int r = 0; r < K1R; r++) acc[r] = bq[col];
            for (int cs = 0; cs < CSD; cs++) {
                float w = Wq[(size_t)cs * HC + col];
                #pragma unroll
                for (int r = 0; r < K1R; r++) acc[r] += ssh[r*CSD+cs] * w;
            }
            #pragma unroll
            for (int r = 0; r < K1R; r++) g_q[(size_t)(bn0+r) * HC + col] = acc[r];
        } else if (col < 3*HC) {
            int j2 = col - HC;
            #pragma unroll
            for (int r = 0; r < K1R; r++) acc[r] = bkv[j2];
            for (int cs = 0; cs < CSD; cs++) {
                float w = Wkv[(size_t)cs * (2*HC) + j2];
                #pragma unroll
                for (int r = 0; r < K1R; r++) acc[r] += ssh[r*CSD+cs] * w;
            }
            int h = j2 >> 5, rr = j2 & 31;
            #pragma unroll
            for (int r = 0; r < K1R; r++) {
                if (rr < NC) g_k[(size_t)(bn0+r) * HC + h * NC + rr] = acc[r];
                else         g_v[(size_t)(bn0+r) * HC + h * NC + (rr - NC)] = acc[r];
            }
        } else if (col < 600) {
            int c2 = col - 576;
            #pragma unroll
            for (int r = 0; r < K1R; r++) acc[r] = bpq[c2];
            for (int cs = 0; cs < CSD; cs++) {
                float w = Wpq[(size_t)cs * (NP*3) + c2];
                #pragma unroll
                for (int r = 0; r < K1R; r++) acc[r] += snsh[r*CSD+cs] * w;
            }
            #pragma unroll
            for (int r = 0; r < K1R; r++) g_qpts[(size_t)(bn0+r) * (NP*3) + c2] = acc[r];
        } else if (col < 624) {
            int c2 = col - 600;
            #pragma unroll
            for (int r = 0; r < K1R; r++) acc[r] = bpv[c2];
            for (int cs = 0; cs < CSD; cs++) {
                float w = Wpv[(size_t)cs * (NP*3) + c2];
                #pragma unroll
                for (int r = 0; r < K1R; r++) acc[r] += snsh[r*CSD+cs] * w;
            }
            #pragma unroll
            for (int r = 0; r < K1R; r++) g_vpts[(size_t)(bn0+r) * (NP*3) + c2] = acc[r];
        } else {
            int c2 = col - 624;
            #pragma unroll
            for (int r = 0; r < K1R; r++) acc[r] = bkvp[c2];
            for (int cs = 0; cs < CSD; cs++) {
                float w = Wkvp[(size_t)cs * HPV3 + c2];
                #pragma unroll
                for (int r = 0; r < K1R; r++) acc[r] += ssh[r*CSD+cs] * w;
            }
            #pragma unroll
            for (int r = 0; r < K1R; r++) kvpsh[r*HPV3 + c2] = acc[r];
        }
    }
    __syncthreads();

    for (int t = tid; t < K1R*HPV3; t += blockDim.x) {
        int r = t / HPV3, e = t - r*HPV3;
        int kidx = e / 3, x = e % 3;
        int bn = bn0 + r;
        const float* rp = rot + (size_t)bn * 9;
        const float* tp = trans + (size_t)bn * 3;
        float vv = tp[x] * 0.1f;
        #pragma unroll
        for (int y = 0; y < 3; y++) vv += rp[x * 3 + y] * kvpsh[r*HPV3 + kidx * 3 + y];
        g_vg[(size_t)bn * HPV3 + e] = vv;
    }
}

// ================= K2: pair stage (JT=64, 4x4 float4 core, fused softmax) =====
// shared layout (floats)
#define OFF_WG    0          // [128][64] 8192
#define OFF_W1    8192       // [64][64]  4096 -> 12288
#define OFF_W2    12288      // [64][12]  768  -> 13056
#define OFF_WVL   13056      // 128 -> 13184
#define OFF_MEAN  13184
#define OFF_ISTD  13200
#define OFF_BG    13216
#define OFF_B1    13280
#define OFF_B2    13344      // 12 -> 13356
#define OFF_HW    13356      // 12 -> 13368
#define OFF_ROTI  13368      // 9  -> 13377
#define OFF_TI    13377      // 3  -> 13380
#define OFF_MASKI 13380      // 1  -> 13381 (pad to 13384)
#define OFF_QPTS  13384      // 24 -> 13408
#define OFF_QVL   13408      // 24 -> 13432
#define OFF_QI    13436      // 192 -> 13628 (pad to 13632)
#define OFF_VLOC  13632      // [64][25] -> 15232
#define OFF_VLEN  15232      // [64][8]  -> 15744
#define OFF_GAU   15744      // [64][132]-> 24192 (reused for h1; stride 132 %4==0)
#define OFF_GB    24192      // [64][68] -> 28544
#define OFF_LOG   28544      // [12][514]-> 34712
#define SMEM2_FLOATS 34712
#define SMEM2_BYTES  (SMEM2_FLOATS * 4)
#define JT 64

__global__ void k2_pair(const float* __restrict__ rot,
                        const float* __restrict__ trans,
                        const float* __restrict__ mask,
                        const float* __restrict__ head_weights,
                        const float* __restrict__ Wvl,
                        const float* __restrict__ gbf_means,
                        const float* __restrict__ gbf_stds,
                        const float* __restrict__ Wg, const float* __restrict__ bg,
                        const float* __restrict__ W1, const float* __restrict__ b1,
                        const float* __restrict__ W2, const float* __restrict__ b2,
                        float* __restrict__ g_out)
{
    extern __shared__ float sh[];
    int bi = blockIdx.x;
    int b = bi >> 9, i = bi & 511;
    int tid = threadIdx.x;

    for (int t = tid; t < 8192; t += 256) sh[OFF_WG + t] = Wg[t];
    for (int t = tid; t < 4096; t += 256) sh[OFF_W1 + t] = W1[t];
    for (int t = tid; t < 768;  t += 256) sh[OFF_W2 + t] = W2[t];
    if (tid < 128) sh[OFF_WVL + tid] = Wvl[tid];
    if (tid < NK) {
        sh[OFF_MEAN + tid] = gbf_means[tid];
        sh[OFF_ISTD + tid] = 1.0f / gbf_stds[tid];
    }
    if (tid < NG) { sh[OFF_BG + tid] = bg[tid]; sh[OFF_B1 + tid] = b1[tid]; }
    if (tid < NH) {
        sh[OFF_B2 + tid] = b2[tid];
        float x = head_weights[tid];
        float sp = logf(1.0f + expf(x));
        sh[OFF_HW + tid] = sp * (-0.11785113f);   // softplus * sqrt(1/18) * -0.5
    }
    if (tid < 9) sh[OFF_ROTI + tid] = rot[(size_t)bi * 9 + tid];
    if (tid < 3) sh[OFF_TI + tid] = trans[(size_t)bi * 3 + tid];
    if (tid < 24) sh[OFF_QPTS + tid] = g_qpts[(size_t)bi * 24 + tid];
    if (tid == 0) sh[OFF_MASKI] = mask[bi];
    if (tid < HC) sh[OFF_QI + tid] = g_q[(size_t)bi * HC + tid];
    __syncthreads();

    if (tid < 24) {  // q-contribution of Wvl (j-independent)
        int o = tid / 3, x = tid % 3;
        float acc = 0.f;
        #pragma unroll
        for (int p = 0; p < NP; p++)
            acc += sh[OFF_WVL + o * 16 + 8 + p] * sh[OFF_QPTS + p * 3 + x];
        sh[OFF_QVL + tid] = acc;
    }
    __syncthreads();

    float ti0 = sh[OFF_TI + 0], ti1 = sh[OFF_TI + 1], ti2 = sh[OFF_TI + 2];
    float mi = sh[OFF_MASKI];
    int ty = tid >> 4, tx = tid & 15;

    const float4* WG4 = (const float4*)(sh + OFF_WG);
    const float4* W14 = (const float4*)(sh + OFF_W1);

    for (int j0 = 0; j0 < NN; j0 += JT) {
        // ---- A: v_loc ----
        {
            int jj = tid >> 2, qq = tid & 3;
            int j = j0 + jj;
            const float* rj = rot + ((size_t)b * NN + j) * 9;
            const float* tj = trans + ((size_t)b * NN + j) * 3;
            float R[3][3], tr[3];
            #pragma unroll
            for (int x = 0; x < 3; x++) {
                float a0 = sh[OFF_ROTI + 0*3 + x];
                float a1 = sh[OFF_ROTI + 1*3 + x];
                float a2 = sh[OFF_ROTI + 2*3 + x];
                #pragma unroll
                for (int z = 0; z < 3; z++)
                    R[x][z] = a0 * rj[0*3+z] + a1 * rj[1*3+z] + a2 * rj[2*3+z];
                tr[x] = a0 * (tj[0] - ti0) + a1 * (tj[1] - ti1) + a2 * (tj[2] - ti2);
            }
            #pragma unroll
            for (int pp = 0; pp < 2; pp++) {
                int p = qq * 2 + pp;
                const float* vp = g_vpts + ((size_t)b * NN + j) * 24 + p * 3;
                float v0 = vp[0], v1 = vp[1], v2 = vp[2];
                #pragma unroll
                for (int x = 0; x < 3; x++)
                    sh[OFF_VLOC + jj*25 + p*3 + x] = R[x][0]*v0 + R[x][1]*v1 + R[x][2]*v2 + tr[x];
            }
        }
        __syncthreads();
        // ---- B: vec + vlen ----
        {
            int jj = tid >> 2, qq = tid & 3;
            const float* vl = sh + OFF_VLOC + jj*25;
            #pragma unroll
            for (int oo = 0; oo < 2; oo++) {
                int o = qq * 2 + oo;
                float vx = sh[OFF_QVL + o*3+0] + vl[o*3+0];
                float vy = sh[OFF_QVL + o*3+1] + vl[o*3+1];
                float vz = sh[OFF_QVL + o*3+2] + vl[o*3+2];
                #pragma unroll
                for (int p = 0; p < NP; p++) {
                    float w_ = sh[OFF_WVL + o * 16 + p];
                    vx += w_ * vl[p*3+0];
                    vy += w_ * vl[p*3+1];
                    vz += w_ * vl[p*3+2];
                }
                sh[OFF_VLEN + jj*8 + o] = sqrtf(vx*vx + vy*vy + vz*vz + 1e-8f);
            }
        }
        __syncthreads();
        // ---- C: gauss [64][128] ----
        #pragma unroll
        for (int it = 0; it < 32; it++) {
            int flat = tid + 256 * it;
            int jj = flat >> 7, m = flat & 127;
            int p = m >> 4, kk = m & 15;
            float d = (sh[OFF_VLEN + jj*8 + p] - sh[OFF_MEAN + kk]) * sh[OFF_ISTD + kk];
            sh[OFF_GAU + jj*132 + m] = __expf(-0.5f * d * d);
        }
        __syncthreads();
        // ---- D: g[64][64] = gauss @ Wg + bg (4x4 tile, float4 acts) ----
        {
            float acc[4][4];
            #pragma unroll
            for (int r = 0; r < 4; r++)
                #pragma unroll
                for (int c = 0; c < 4; c++) acc[r][c] = sh[OFF_BG + tx*4 + c];
            const float4* ga0 = (const float4*)(sh + OFF_GAU + (4*ty+0)*132);
            const float4* ga1 = (const float4*)(sh + OFF_GAU + (4*ty+1)*132);
            const float4* ga2 = (const float4*)(sh + OFF_GAU + (4*ty+2)*132);
            const float4* ga3 = (const float4*)(sh + OFF_GAU + (4*ty+3)*132);
            #pragma unroll 2
            for (int m4 = 0; m4 < 32; m4++) {
                float4 a0 = ga0[m4], a1 = ga1[m4], a2 = ga2[m4], a3 = ga3[m4];
                #pragma unroll
                for (int u = 0; u < 4; u++) {
                    float4 wv = WG4[(m4*4+u) * 16 + tx];
                    float g0 = (u==0)?a0.x:(u==1)?a0.y:(u==2)?a0.z:a0.w;
                    float g1 = (u==0)?a1.x:(u==1)?a1.y:(u==2)?a1.z:a1.w;
                    float g2 = (u==0)?a2.x:(u==1)?a2.y:(u==2)?a2.z:a2.w;
                    float g3 = (u==0)?a3.x:(u==1)?a3.y:(u==2)?a3.z:a3.w;
                    acc[0][0] += g0*wv.x; acc[0][1] += g0*wv.y; acc[0][2] += g0*wv.z; acc[0][3] += g0*wv.w;
                    acc[1][0] += g1*wv.x; acc[1][1] += g1*wv.y; acc[1][2] += g1*wv.z; acc[1][3] += g1*wv.w;
                    acc[2][0] += g2*wv.x; acc[2][1] += g2*wv.y; acc[2][2] += g2*wv.z; acc[2][3] += g2*wv.w;
                    acc[3][0] += g3*wv.x; acc[3][1] += g3*wv.y; acc[3][2] += g3*wv.z; acc[3][3] += g3*wv.w;
                }
            }
            #pragma unroll
            for (int r = 0; r < 4; r++) {
                int jj = 4*ty + r;
                float4 v4 = make_float4(acc[r][0], acc[r][1], acc[r][2], acc[r][3]);
                *(float4*)(sh + OFF_GB + jj*68 + tx*4) = v4;
                *(float4*)(g_out + ((size_t)bi * NN + j0 + jj) * NG + tx*4) = v4;
            }
        }
        __syncthreads();
        // ---- E: h1[64][64] = relu(g @ W1 + b1), overwrite GAU ----
        {
            float acc[4][4];
            #pragma unroll
            for (int r = 0; r < 4; r++)
                #pragma unroll
                for (int c = 0; c < 4; c++) acc[r][c] = sh[OFF_B1 + tx*4 + c];
            const float4* gb0 = (const float4*)(sh + OFF_GB + (4*ty+0)*68);
            const float4* gb1 = (const float4*)(sh + OFF_GB + (4*ty+1)*68);
            const float4* gb2 = (const float4*)(sh + OFF_GB + (4*ty+2)*68);
            const float4* gb3 = (const float4*)(sh + OFF_GB + (4*ty+3)*68);
            #pragma unroll 2
            for (int m4 = 0; m4 < 16; m4++) {
                float4 a0 = gb0[m4], a1 = gb1[m4], a2 = gb2[m4], a3 = gb3[m4];
                #pragma unroll
                for (int u = 0; u < 4; u++) {
                    float4 wv = W14[(m4*4+u) * 16 + tx];
                    float g0 = (u==0)?a0.x:(u==1)?a0.y:(u==2)?a0.z:a0.w;
                    float g1 = (u==0)?a1.x:(u==1)?a1.y:(u==2)?a1.z:a1.w;
                    float g2 = (u==0)?a2.x:(u==1)?a2.y:(u==2)?a2.z:a2.w;
                    float g3 = (u==0)?a3.x:(u==1)?a3.y:(u==2)?a3.z:a3.w;
                    acc[0][0] += g0*wv.x; acc[0][1] += g0*wv.y; acc[0][2] += g0*wv.z; acc[0][3] += g0*wv.w;
                    acc[1][0] += g1*wv.x; acc[1][1] += g1*wv.y; acc[1][2] += g1*wv.z; acc[1][3] += g1*wv.w;
                    acc[2][0] += g2*wv.x; acc[2][1] += g2*wv.y; acc[2][2] += g2*wv.z; acc[2][3] += g2*wv.w;
                    acc[3][0] += g3*wv.x; acc[3][1] += g3*wv.y; acc[3][2] += g3*wv.z; acc[3][3] += g3*wv.w;
                }
            }
            __syncthreads();   // gauss fully consumed; safe to overwrite GAU with h1
            #pragma unroll
            for (int r = 0; r < 4; r++) {
                int jj = 4*ty + r;
                *(float4*)(sh + OFF_GAU + jj*132 + tx*4) =
                    make_float4(fmaxf(acc[r][0],0.f), fmaxf(acc[r][1],0.f),
                                fmaxf(acc[r][2],0.f), fmaxf(acc[r][3],0.f));
            }
        }
        __syncthreads();
        // ---- F: vfn + qk + dist -> logits (into smem) ----
        for (int idx = tid; idx < JT * NH; idx += 256) {
            int jj = idx / NH, h = idx - jj * NH;
            int j = j0 + jj;
            float acc = sh[OFF_B2 + h];
            const float* h1 = sh + OFF_GAU + jj*132;
            #pragma unroll 8
            for (int m = 0; m < 64; m++)
                acc += h1[m] * sh[OFF_W2 + m * NH + h];
            const float4* kp = (const float4*)(g_k + ((size_t)b * NN + j) * HC + h * NC);
            const float4* qp = (const float4*)(sh + OFF_QI + h * NC);
            float qk = 0.f;
            #pragma unroll
            for (int c = 0; c < 4; c++) {
                float4 kk4 = kp[c], qq4 = qp[c];
                qk += qq4.x*kk4.x + qq4.y*kk4.y + qq4.z*kk4.z + qq4.w*kk4.w;
            }
            const float* tj = trans + ((size_t)b * NN + j) * 3;
            float d0 = (tj[0] - ti0) * 0.1f;
            float d1 = (tj[1] - ti1) * 0.1f;
            float d2 = (tj[2] - ti2) * 0.1f;
            float pd = d0*d0 + d1*d1 + d2*d2;
            float mj = mask[(size_t)b * NN + j];
            sh[OFF_LOG + h*514 + j] = qk * 0.125f + acc * 0.5f + pd * sh[OFF_HW + h]
                                    + 100000.0f * (mi * mj - 1.0f);
        }
        __syncthreads();
    }

    // ---- fused softmax over j per head, write probs coalesced ----
    {
        int wid = tid >> 5, lane = tid & 31;
        for (int h = wid; h < NH; h += 8) {
            float* row = sh + OFF_LOG + h*514;
            float mx = -1e30f;
            for (int j = lane; j < NN; j += 32) mx = fmaxf(mx, row[j]);
            #pragma unroll
            for (int o = 16; o > 0; o >>= 1) mx = fmaxf(mx, __shfl_xor_sync(0xffffffffu, mx, o));
            float sm = 0.f;
            for (int j = lane; j < NN; j += 32) {
                float e = __expf(row[j] - mx);
                row[j] = e;
                sm += e;
            }
            #pragma unroll
            for (int o = 16; o > 0; o >>= 1) sm += __shfl_xor_sync(0xffffffffu, sm, o);
            float inv = 1.0f / sm;
            float* dst = g_probs + ((((size_t)b * NH + h) * NN) + i) * NN;
            for (int j = lane; j < NN; j += 32) dst[j] = row[j] * inv;
        }
    }
}

// ================= K4: attention-weighted sums, tiled GEMM =================
// block = (b, h, itile of 64); out cols = 16 (v) + 24 (vg) = 40
__global__ void k4_attn()
{
    __shared__ float a_sh[64*68];    // [i][j] pad 68
    __shared__ float v_sh[64*41];    // [j][col] pad 41

    int blk = blockIdx.x;
    int it = blk & 7;
    int h  = (blk >> 3) % 12;
    int b  = blk / (8 * 12);
    int i0 = it * 64;
    int tid = threadIdx.x;

    int q  = tid & 7;        // 5 cols each
    int ip = tid >> 3;       // i in {ip, ip+32}
    float acc[2][5];
    #pragma unroll
    for (int u = 0; u < 2; u++)
        #pragma unroll
        for (int c = 0; c < 5; c++) acc[u][c] = 0.f;

    const float* Arow = g_probs + (((size_t)b * NH + h) * NN + i0) * NN;

    for (int jt = 0; jt < NN; jt += 64) {
        for (int idx = tid; idx < 64*64; idx += 256) {
            int ii = idx >> 6, jj = idx & 63;
            a_sh[ii*68 + jj] = Arow[(size_t)ii * NN + jt + jj];
        }
        for (int idx = tid; idx < 64*40; idx += 256) {
            int jj = idx / 40, c = idx - jj*40;
            int j = jt + jj;
            float v;
            if (c < 16) v = g_v [((size_t)b * NN + j) * HC   + h * NC + c];
            else        v = g_vg[((size_t)b * NN + j) * HPV3 + h * 24 + (c - 16)];
            v_sh[jj*41 + c] = v;
        }
        __syncthreads();
        #pragma unroll 4
        for (int jj = 0; jj < 64; jj++) {
            float a0 = a_sh[ip*68 + jj];
            float a1 = a_sh[(ip+32)*68 + jj];
            const float* vp = v_sh + jj*41 + q*5;
            #pragma unroll
            for (int c = 0; c < 5; c++) {
                float v = vp[c];
                acc[0][c] += a0 * v;
                acc[1][c] += a1 * v;
            }
        }
        __syncthreads();
    }

    #pragma unroll
    for (int u = 0; u < 2; u++) {
        int ig = i0 + ip + 32*u;
        #pragma unroll
        for (int c = 0; c < 5; c++) {
            int col = q*5 + c;
            if (col < 16) g_o  [((size_t)b * NN + ig) * HC   + h * NC + col]      = acc[u][c];
            else          g_opt[((size_t)b * NN + ig) * HPV3 + h * 24 + (col-16)] = acc[u][c];
        }
    }
}

// ================= K5: final features + output GEMV, 4 rows/block =================
#define K5R 4
__global__ void k5_out(const float* __restrict__ rot,
                       const float* __restrict__ trans,
                       const float* __restrict__ Wout,
                       const float* __restrict__ bout,
                       float* __restrict__ sout)
{
    __shared__ float feats[K5R*576];
    int bi0 = blockIdx.x * K5R;
    int tid = threadIdx.x;

    for (int idx = tid; idx < K5R*HC; idx += 384) {
        int r = idx / HC, c = idx - r*HC;
        feats[r*576 + c] = g_o[(size_t)(bi0+r) * HC + c];
    }
    for (int idx = tid; idx < K5R*96; idx += 384) {
        int r = idx / 96, kidx = idx - r*96;
        int bi = bi0 + r;
        const float* rp = rot + (size_t)bi * 9;
        const float* tp = trans + (size_t)bi * 3;
        float oy0 = g_opt[(size_t)bi * HPV3 + kidx*3+0] - tp[0] * 0.1f;
        float oy1 = g_opt[(size_t)bi * HPV3 + kidx*3+1] - tp[1] * 0.1f;
        float oy2 = g_opt[(size_t)bi * HPV3 + kidx*3+2] - tp[2] * 0.1f;
        float l0 = rp[0]*oy0 + rp[3]*oy1 + rp[6]*oy2;
        float l1 = rp[1]*oy0 + rp[4]*oy1 + rp[7]*oy2;
        float l2 = rp[2]*oy0 + rp[5]*oy1 + rp[8]*oy2;
        feats[r*576 + 192 + kidx] = l0;
        feats[r*576 + 288 + kidx] = l1;
        feats[r*576 + 384 + kidx] = l2;
        feats[r*576 + 480 + kidx] = sqrtf(l0*l0 + l1*l1 + l2*l2 + 1e-8f);
    }
    __syncthreads();

    int cs = tid;  // blockDim = 384
    float acc[K5R];
    float bb = bout[cs];
    #pragma unroll
    for (int r = 0; r < K5R; r++) acc[r] = bb;
    for (int f0 = 0; f0 < 576; f0 += 8) {
        float w[8];
        #pragma unroll
        for (int u = 0; u < 8; u++) w[u] = Wout[(size_t)(f0+u) * CSD + cs];
        #pragma unroll
        for (int u = 0; u < 8; u++) {
            #pragma unroll
            for (int r = 0; r < K5R; r++) acc[r] += feats[r*576 + f0 + u] * w[u];
        }
    }
    #pragma unroll
    for (int r = 0; r < K5R; r++)
        sout[(size_t)(bi0+r) * CSD + cs] = acc[r];
}

// ================= launch =================
extern "C" void kernel_launch(void* const* d_in, const int* in_sizes, int n_in,
                              void* d_out, int out_size)
{
    const float* s        = (const float*)d_in[0];
    const float* rot      = (const float*)d_in[1];
    const float* trans    = (const float*)d_in[2];
    const float* mask     = (const float*)d_in[3];
    const float* Wq       = (const float*)d_in[4];
    const float* bq       = (const float*)d_in[5];
    const float* Wkv      = (const float*)d_in[6];
    const float* bkv      = (const float*)d_in[7];
    const float* head_w   = (const float*)d_in[8];
    const float* ln_g     = (const float*)d_in[9];
    const float* ln_b     = (const float*)d_in[10];
    const float* Wpq      = (const float*)d_in[11];
    const float* bpq      = (const float*)d_in[12];
    const float* Wpv      = (const float*)d_in[13];
    const float* bpv      = (const float*)d_in[14];
    const float* Wvl      = (const float*)d_in[15];
    const float* gbf_mean = (const float*)d_in[16];
    const float* gbf_std  = (const float*)d_in[17];
    const float* Wg       = (const float*)d_in[18];
    const float* bg       = (const float*)d_in[19];
    const float* W1       = (const float*)d_in[20];
    const float* b1       = (const float*)d_in[21];
    const float* W2       = (const float*)d_in[22];
    const float* b2       = (const float*)d_in[23];
    const float* Wkvp     = (const float*)d_in[24];
    const float* bkvp     = (const float*)d_in[25];
    const float* Wout     = (const float*)d_in[26];
    const float* bout     = (const float*)d_in[27];

    float* out = (float*)d_out;
    float* sout_part = out;                              // (B,N,CS)
    float* g_part = out + (size_t)NB * NN * CSD;         // (B,N,N,G)

    cudaFuncSetAttribute((const void*)k2_pair,
                         cudaFuncAttributeMaxDynamicSharedMemorySize, SMEM2_BYTES);

    k1_project<<<NB * NN / K1R, 256>>>(s, rot, trans, Wq, bq, Wkv, bkv,
                                       ln_g, ln_b, Wpq, bpq, Wpv, bpv, Wkvp, bkvp);
    k2_pair<<<NB * NN, 256, SMEM2_BYTES>>>(rot, trans, mask, head_w, Wvl,
                                           gbf_mean, gbf_std, Wg, bg, W1, b1,
                                           W2, b2, g_part);
    k4_attn<<<NB * NH * (NN/64), 256>>>();
    k5_out<<<NB * NN / K5R, 384>>>(rot, trans, Wout, bout, sout_part);
}

// round 10
// speedup vs baseline: 1.2252x; 1.0422x over previous
#include <cuda_runtime.h>
#include <math.h>

// Problem dims
#define NB 2
#define NN 512
#define CSD 384
#define NH 12
#define NC 16
#define NP 8
#define NPV 8
#define NK 16
#define NG 64
#define HC (NH*NC)          // 192
#define HPV3 (NH*NPV*3)     // 288

// ---------------- scratch (device globals) -------------
__device__ __align__(16) float g_q   [NB*NN*HC];
__device__ __align__(16) float g_k   [NB*NN*HC];
__device__ __align__(16) float g_v   [NB*NN*HC];
__device__ __align__(16) float g_qpts[NB*NN*NP*3];
__device__ __align__(16) float g_vpts[NB*NN*NP*3];
__device__ __align__(16) float g_vg  [NB*NN*HPV3];
__device__ __align__(16) float g_logits[(size_t)NB*NH*NN*NN];
__device__ __align__(16) float g_o   [NB*NN*HC];
__device__ __align__(16) float g_opt [NB*NN*HPV3];

// ================= K1: per-row projections, 8 rows per block =================
#define K1R 8
__global__ void k1_project(const float* __restrict__ s,
                           const float* __restrict__ rot,
                           const float* __restrict__ trans,
                           const float* __restrict__ Wq,  const float* __restrict__ bq,
                           const float* __restrict__ Wkv, const float* __restrict__ bkv,
                           const float* __restrict__ ln_g,const float* __restrict__ ln_b,
                           const float* __restrict__ Wpq, const float* __restrict__ bpq,
                           const float* __restrict__ Wpv, const float* __restrict__ bpv,
                           const float* __restrict__ Wkvp,const float* __restrict__ bkvp)
{
    __shared__ float ssh [K1R*CSD];
    __shared__ float snsh[K1R*CSD];
    __shared__ float kvpsh[K1R*HPV3];

    int bn0 = blockIdx.x * K1R;
    int tid = threadIdx.x;
    int wid = tid >> 5, lane = tid & 31;

    for (int idx = tid; idx < K1R*CSD; idx += blockDim.x)
        ssh[idx] = s[(size_t)bn0 * CSD + idx];
    __syncthreads();

    {
        int r = wid;
        const float* row = ssh + r * CSD;
        float lsum = 0.f;
        for (int i = lane; i < CSD; i += 32) lsum += row[i];
        #pragma unroll
        for (int o = 16; o > 0; o >>= 1) lsum += __shfl_xor_sync(0xffffffffu, lsum, o);
        float mean = lsum * (1.0f / CSD);
        float lvar = 0.f;
        for (int i = lane; i < CSD; i += 32) { float d = row[i] - mean; lvar += d * d; }
        #pragma unroll
        for (int o = 16; o > 0; o >>= 1) lvar += __shfl_xor_sync(0xffffffffu, lvar, o);
        float inv = rsqrtf(lvar * (1.0f / CSD) + 1e-5f);
        for (int i = lane; i < CSD; i += 32)
            snsh[r * CSD + i] = (row[i] - mean) * inv * ln_g[i] + ln_b[i];
    }
    __syncthreads();

    for (int col = tid; col < 912; col += blockDim.x) {
        float acc[K1R];
        if (col < HC) {
            #pragma unroll
            for (int r = 0; r < K1R; r++) acc[r] = bq[col];
            for (int cs = 0; cs < CSD; cs++) {
                float w = Wq[(size_t)cs * HC + col];
                #pragma unroll
                for (int r = 0; r < K1R; r++) acc[r] += ssh[r*CSD+cs] * w;
            }
            #pragma unroll
            for (int r = 0; r < K1R; r++) g_q[(size_t)(bn0+r) * HC + col] = acc[r];
        } else if (col < 3*HC) {
            int j2 = col - HC;
            #pragma unroll
            for (int r = 0; r < K1R; r++) acc[r] = bkv[j2];
            for (int cs = 0; cs < CSD; cs++) {
                float w = Wkv[(size_t)cs * (2*HC) + j2];
                #pragma unroll
                for (int r = 0; r < K1R; r++) acc[r] += ssh[r*CSD+cs] * w;
            }
            int h = j2 >> 5, rr = j2 & 31;
            #pragma unroll
            for (int r = 0; r < K1R; r++) {
                if (rr < NC) g_k[(size_t)(bn0+r) * HC + h * NC + rr] = acc[r];
                else         g_v[(size_t)(bn0+r) * HC + h * NC + (rr - NC)] = acc[r];
            }
        } else if (col < 600) {
            int c2 = col - 576;
            #pragma unroll
            for (int r = 0; r < K1R; r++) acc[r] = bpq[c2];
            for (int cs = 0; cs < CSD; cs++) {
                float w = Wpq[(size_t)cs * (NP*3) + c2];
                #pragma unroll
                for (int r = 0; r < K1R; r++) acc[r] += snsh[r*CSD+cs] * w;
            }
            #pragma unroll
            for (int r = 0; r < K1R; r++) g_qpts[(size_t)(bn0+r) * (NP*3) + c2] = acc[r];
        } else if (col < 624) {
            int c2 = col - 600;
            #pragma unroll
            for (int r = 0; r < K1R; r++) acc[r] = bpv[c2];
            for (int cs = 0; cs < CSD; cs++) {
                float w = Wpv[(size_t)cs * (NP*3) + c2];
                #pragma unroll
                for (int r = 0; r < K1R; r++) acc[r] += snsh[r*CSD+cs] * w;
            }
            #pragma unroll
            for (int r = 0; r < K1R; r++) g_vpts[(size_t)(bn0+r) * (NP*3) + c2] = acc[r];
        } else {
            int c2 = col - 624;
            #pragma unroll
            for (int r = 0; r < K1R; r++) acc[r] = bkvp[c2];
            for (int cs = 0; cs < CSD; cs++) {
                float w = Wkvp[(size_t)cs * HPV3 + c2];
                #pragma unroll
                for (int r = 0; r < K1R; r++) acc[r] += ssh[r*CSD+cs] * w;
            }
            #pragma unroll
            for (int r = 0; r < K1R; r++) kvpsh[r*HPV3 + c2] = acc[r];
        }
    }
    __syncthreads();

    for (int t = tid; t < K1R*HPV3; t += blockDim.x) {
        int r = t / HPV3, e = t - r*HPV3;
        int kidx = e / 3, x = e % 3;
        int bn = bn0 + r;
        const float* rp = rot + (size_t)bn * 9;
        const float* tp = trans + (size_t)bn * 3;
        float vv = tp[x] * 0.1f;
        #pragma unroll
        for (int y = 0; y < 3; y++) vv += rp[x * 3 + y] * kvpsh[r*HPV3 + kidx * 3 + y];
        g_vg[(size_t)bn * HPV3 + e] = vv;
    }
}

// ============ K2: pair stage (JT=64, 4x4 core, weights from L1, 3 blk/SM) =====
// shared layout (floats) — only activations + small constants
#define OFF_WVL   0          // 128 -> 128
#define OFF_MEAN  128        // 16
#define OFF_ISTD  144        // 16
#define OFF_BG    160        // 64
#define OFF_B1    224        // 64
#define OFF_B2    288        // 12
#define OFF_HW    300        // 12
#define OFF_ROTI  312        // 9
#define OFF_TI    321        // 3
#define OFF_QPTS  324        // 24
#define OFF_QVL   348        // 24
#define OFF_MASKI 372        // 1 (pad to 376)
#define OFF_QI    376        // 192 -> 568
#define OFF_VLOC  568        // [64][25] -> 2168
#define OFF_VLEN  2168       // [64][8]  -> 2680
#define OFF_GAU   2680       // [64][132]-> 11128 (reused for h1)
#define OFF_GB    11128      // [64][68] -> 15480
#define SMEM2_FLOATS 15480
#define SMEM2_BYTES  (SMEM2_FLOATS * 4)   // 61,920 B -> 3 blocks/SM
#define JT 64

__global__ void __launch_bounds__(256, 3)
k2_pair(const float* __restrict__ rot,
        const float* __restrict__ trans,
        const float* __restrict__ mask,
        const float* __restrict__ head_weights,
        const float* __restrict__ Wvl,
        const float* __restrict__ gbf_means,
        const float* __restrict__ gbf_stds,
        const float* __restrict__ Wg, const float* __restrict__ bg,
        const float* __restrict__ W1, const float* __restrict__ b1,
        const float* __restrict__ W2, const float* __restrict__ b2,
        float* __restrict__ g_out)
{
    extern __shared__ float sh[];
    int bi = blockIdx.x;
    int b = bi >> 9, i = bi & 511;
    int tid = threadIdx.x;

    if (tid < 128) sh[OFF_WVL + tid] = Wvl[tid];
    if (tid < NK) {
        sh[OFF_MEAN + tid] = gbf_means[tid];
        sh[OFF_ISTD + tid] = 1.0f / gbf_stds[tid];
    }
    if (tid < NG) { sh[OFF_BG + tid] = bg[tid]; sh[OFF_B1 + tid] = b1[tid]; }
    if (tid < NH) {
        sh[OFF_B2 + tid] = b2[tid];
        float x = head_weights[tid];
        float sp = logf(1.0f + expf(x));
        sh[OFF_HW + tid] = sp * (-0.11785113f);   // softplus * sqrt(1/18) * -0.5
    }
    if (tid < 9) sh[OFF_ROTI + tid] = rot[(size_t)bi * 9 + tid];
    if (tid < 3) sh[OFF_TI + tid] = trans[(size_t)bi * 3 + tid];
    if (tid < 24) sh[OFF_QPTS + tid] = g_qpts[(size_t)bi * 24 + tid];
    if (tid == 0) sh[OFF_MASKI] = mask[bi];
    if (tid < HC) sh[OFF_QI + tid] = g_q[(size_t)bi * HC + tid];
    __syncthreads();

    if (tid < 24) {  // q-contribution of Wvl (j-independent)
        int o = tid / 3, x = tid % 3;
        float acc = 0.f;
        #pragma unroll
        for (int p = 0; p < NP; p++)
            acc += sh[OFF_WVL + o * 16 + 8 + p] * sh[OFF_QPTS + p * 3 + x];
        sh[OFF_QVL + tid] = acc;
    }
    __syncthreads();

    float ti0 = sh[OFF_TI + 0], ti1 = sh[OFF_TI + 1], ti2 = sh[OFF_TI + 2];
    float mi = sh[OFF_MASKI];
    int ty = tid >> 4, tx = tid & 15;

    // weights served straight from global -> L1 (shared by all blocks on the SM)
    const float4* __restrict__ WG4 = (const float4*)Wg;   // [128][64] -> m*16+tx
    const float4* __restrict__ W14 = (const float4*)W1;   // [64][64]  -> m*16+tx

    for (int j0 = 0; j0 < NN; j0 += JT) {
        // ---- A: v_loc ----
        {
            int jj = tid >> 2, qq = tid & 3;
            int j = j0 + jj;
            const float* rj = rot + ((size_t)b * NN + j) * 9;
            const float* tj = trans + ((size_t)b * NN + j) * 3;
            float R[3][3], tr[3];
            #pragma unroll
            for (int x = 0; x < 3; x++) {
                float a0 = sh[OFF_ROTI + 0*3 + x];
                float a1 = sh[OFF_ROTI + 1*3 + x];
                float a2 = sh[OFF_ROTI + 2*3 + x];
                #pragma unroll
                for (int z = 0; z < 3; z++)
                    R[x][z] = a0 * rj[0*3+z] + a1 * rj[1*3+z] + a2 * rj[2*3+z];
                tr[x] = a0 * (tj[0] - ti0) + a1 * (tj[1] - ti1) + a2 * (tj[2] - ti2);
            }
            #pragma unroll
            for (int pp = 0; pp < 2; pp++) {
                int p = qq * 2 + pp;
                const float* vp = g_vpts + ((size_t)b * NN + j) * 24 + p * 3;
                float v0 = vp[0], v1 = vp[1], v2 = vp[2];
                #pragma unroll
                for (int x = 0; x < 3; x++)
                    sh[OFF_VLOC + jj*25 + p*3 + x] = R[x][0]*v0 + R[x][1]*v1 + R[x][2]*v2 + tr[x];
            }
        }
        __syncthreads();
        // ---- B: vec + vlen ----
        {
            int jj = tid >> 2, qq = tid & 3;
            const float* vl = sh + OFF_VLOC + jj*25;
            #pragma unroll
            for (int oo = 0; oo < 2; oo++) {
                int o = qq * 2 + oo;
                float vx = sh[OFF_QVL + o*3+0] + vl[o*3+0];
                float vy = sh[OFF_QVL + o*3+1] + vl[o*3+1];
                float vz = sh[OFF_QVL + o*3+2] + vl[o*3+2];
                #pragma unroll
                for (int p = 0; p < NP; p++) {
                    float w_ = sh[OFF_WVL + o * 16 + p];
                    vx += w_ * vl[p*3+0];
                    vy += w_ * vl[p*3+1];
                    vz += w_ * vl[p*3+2];
                }
                sh[OFF_VLEN + jj*8 + o] = sqrtf(vx*vx + vy*vy + vz*vz + 1e-8f);
            }
        }
        __syncthreads();
        // ---- C: gauss [64][128] ----
        #pragma unroll
        for (int it = 0; it < 32; it++) {
            int flat = tid + 256 * it;
            int jj = flat >> 7, m = flat & 127;
            int p = m >> 4, kk = m & 15;
            float d = (sh[OFF_VLEN + jj*8 + p] - sh[OFF_MEAN + kk]) * sh[OFF_ISTD + kk];
            sh[OFF_GAU + jj*132 + m] = __expf(-0.5f * d * d);
        }
        __syncthreads();
        // ---- D: g[64][64] = gauss @ Wg + bg (4x4 register tile) ----
        {
            float acc[4][4];
            #pragma unroll
            for (int r = 0; r < 4; r++)
                #pragma unroll
                for (int c = 0; c < 4; c++) acc[r][c] = sh[OFF_BG + tx*4 + c];
            #pragma unroll 4
            for (int m = 0; m < 128; m++) {
                float4 wv = WG4[m * 16 + tx];
                float ga0 = sh[OFF_GAU + (4*ty+0)*132 + m];
                float ga1 = sh[OFF_GAU + (4*ty+1)*132 + m];
                float ga2 = sh[OFF_GAU + (4*ty+2)*132 + m];
                float ga3 = sh[OFF_GAU + (4*ty+3)*132 + m];
                acc[0][0] += ga0*wv.x; acc[0][1] += ga0*wv.y; acc[0][2] += ga0*wv.z; acc[0][3] += ga0*wv.w;
                acc[1][0] += ga1*wv.x; acc[1][1] += ga1*wv.y; acc[1][2] += ga1*wv.z; acc[1][3] += ga1*wv.w;
                acc[2][0] += ga2*wv.x; acc[2][1] += ga2*wv.y; acc[2][2] += ga2*wv.z; acc[2][3] += ga2*wv.w;
                acc[3][0] += ga3*wv.x; acc[3][1] += ga3*wv.y; acc[3][2] += ga3*wv.z; acc[3][3] += ga3*wv.w;
            }
            #pragma unroll
            for (int r = 0; r < 4; r++) {
                int jj = 4*ty + r;
                float4 v4 = make_float4(acc[r][0], acc[r][1], acc[r][2], acc[r][3]);
                *(float4*)(sh + OFF_GB + jj*68 + tx*4) = v4;
                *(float4*)(g_out + ((size_t)bi * NN + j0 + jj) * NG + tx*4) = v4;
            }
        }
        __syncthreads();
        // ---- E: h1[64][64] = relu(g @ W1 + b1), overwrite GAU ----
        {
            float acc[4][4];
            #pragma unroll
            for (int r = 0; r < 4; r++)
                #pragma unroll
                for (int c = 0; c < 4; c++) acc[r][c] = sh[OFF_B1 + tx*4 + c];
            #pragma unroll 4
            for (int m = 0; m < 64; m++) {
                float4 wv = W14[m * 16 + tx];
                float ga0 = sh[OFF_GB + (4*ty+0)*68 + m];
                float ga1 = sh[OFF_GB + (4*ty+1)*68 + m];
                float ga2 = sh[OFF_GB + (4*ty+2)*68 + m];
                float ga3 = sh[OFF_GB + (4*ty+3)*68 + m];
                acc[0][0] += ga0*wv.x; acc[0][1] += ga0*wv.y; acc[0][2] += ga0*wv.z; acc[0][3] += ga0*wv.w;
                acc[1][0] += ga1*wv.x; acc[1][1] += ga1*wv.y; acc[1][2] += ga1*wv.z; acc[1][3] += ga1*wv.w;
                acc[2][0] += ga2*wv.x; acc[2][1] += ga2*wv.y; acc[2][2] += ga2*wv.z; acc[2][3] += ga2*wv.w;
                acc[3][0] += ga3*wv.x; acc[3][1] += ga3*wv.y; acc[3][2] += ga3*wv.z; acc[3][3] += ga3*wv.w;
            }
            __syncthreads();   // gauss fully consumed; safe to overwrite GAU with h1
            #pragma unroll
            for (int r = 0; r < 4; r++) {
                int jj = 4*ty + r;
                *(float4*)(sh + OFF_GAU + jj*132 + tx*4) =
                    make_float4(fmaxf(acc[r][0],0.f), fmaxf(acc[r][1],0.f),
                                fmaxf(acc[r][2],0.f), fmaxf(acc[r][3],0.f));
            }
        }
        __syncthreads();
        // ---- F: vfn + qk + dist -> logits ----
        for (int idx = tid; idx < JT * NH; idx += 256) {
            int jj = idx / NH, h = idx - jj * NH;
            int j = j0 + jj;
            float acc = sh[OFF_B2 + h];
            const float* h1 = sh + OFF_GAU + jj*132;
            #pragma unroll 8
            for (int m = 0; m < 64; m++)
                acc += h1[m] * W2[m * NH + h];
            const float4* kp = (const float4*)(g_k + ((size_t)b * NN + j) * HC + h * NC);
            const float4* qp = (const float4*)(sh + OFF_QI + h * NC);
            float qk = 0.f;
            #pragma unroll
            for (int c = 0; c < 4; c++) {
                float4 kk4 = kp[c], qq4 = qp[c];
                qk += qq4.x*kk4.x + qq4.y*kk4.y + qq4.z*kk4.z + qq4.w*kk4.w;
            }
            const float* tj = trans + ((size_t)b * NN + j) * 3;
            float d0 = (tj[0] - ti0) * 0.1f;
            float d1 = (tj[1] - ti1) * 0.1f;
            float d2 = (tj[2] - ti2) * 0.1f;
            float pd = d0*d0 + d1*d1 + d2*d2;
            float mj = mask[(size_t)b * NN + j];
            float logit = qk * 0.125f + acc * 0.5f + pd * sh[OFF_HW + h]
                        + 100000.0f * (mi * mj - 1.0f);
            g_logits[((((size_t)b * NH + h) * NN) + i) * NN + j] = logit;
        }
        __syncthreads();
    }
}

// ================= K3: softmax over last dim =================
__global__ void k3_softmax()
{
    __shared__ float red[32];
    size_t row = blockIdx.x;
    float* p = g_logits + row * NN;
    int tid = threadIdx.x;
    int lane = tid & 31, wid = tid >> 5;
    float v0 = p[tid], v1 = p[tid + 256];
    float mv = fmaxf(v0, v1);
    #pragma unroll
    for (int o = 16; o > 0; o >>= 1) mv = fmaxf(mv, __shfl_xor_sync(0xffffffffu, mv, o));
    if (lane == 0) red[wid] = mv;
    __syncthreads();
    float mx = (lane < 8) ? red[lane] : -1e30f;
    #pragma unroll
    for (int o = 4; o > 0; o >>= 1) mx = fmaxf(mx, __shfl_xor_sync(0xffffffffu, mx, o));
    mx = __shfl_sync(0xffffffffu, mx, 0);
    if (wid == 0 && lane == 0) red[0] = mx;
    __syncthreads();
    mx = red[0];
    float e0 = __expf(v0 - mx), e1 = __expf(v1 - mx);
    float sv = e0 + e1;
    #pragma unroll
    for (int o = 16; o > 0; o >>= 1) sv += __shfl_xor_sync(0xffffffffu, sv, o);
    __syncthreads();
    if (lane == 0) red[wid] = sv;
    __syncthreads();
    float sm = (lane < 8) ? red[lane] : 0.f;
    #pragma unroll
    for (int o = 4; o > 0; o >>= 1) sm += __shfl_xor_sync(0xffffffffu, sm, o);
    if (wid == 0 && lane == 0) red[0] = sm;
    __syncthreads();
    float inv = 1.0f / red[0];
    p[tid] = e0 * inv;
    p[tid + 256] = e1 * inv;
}

// ================= K4: attention-weighted sums, tiled GEMM =================
// block = (b, h, itile of 64); out cols = 16 (v) + 24 (vg) = 40
__global__ void k4_attn()
{
    __shared__ float a_sh[64*68];    // [i][j] pad 68
    __shared__ float v_sh[64*41];    // [j][col] pad 41

    int blk = blockIdx.x;
    int it = blk & 7;
    int h  = (blk >> 3) % 12;
    int b  = blk / (8 * 12);
    int i0 = it * 64;
    int tid = threadIdx.x;

    int q  = tid & 7;        // 5 cols each
    int ip = tid >> 3;       // i in {ip, ip+32}
    float acc[2][5];
    #pragma unroll
    for (int u = 0; u < 2; u++)
        #pragma unroll
        for (int c = 0; c < 5; c++) acc[u][c] = 0.f;

    const float* Arow = g_logits + (((size_t)b * NH + h) * NN + i0) * NN;

    for (int jt = 0; jt < NN; jt += 64) {
        for (int idx = tid; idx < 64*64; idx += 256) {
            int ii = idx >> 6, jj = idx & 63;
            a_sh[ii*68 + jj] = Arow[(size_t)ii * NN + jt + jj];
        }
        for (int idx = tid; idx < 64*40; idx += 256) {
            int jj = idx / 40, c = idx - jj*40;
            int j = jt + jj;
            float v;
            if (c < 16) v = g_v [((size_t)b * NN + j) * HC   + h * NC + c];
            else        v = g_vg[((size_t)b * NN + j) * HPV3 + h * 24 + (c - 16)];
            v_sh[jj*41 + c] = v;
        }
        __syncthreads();
        #pragma unroll 4
        for (int jj = 0; jj < 64; jj++) {
            float a0 = a_sh[ip*68 + jj];
            float a1 = a_sh[(ip+32)*68 + jj];
            const float* vp = v_sh + jj*41 + q*5;
            #pragma unroll
            for (int c = 0; c < 5; c++) {
                float v = vp[c];
                acc[0][c] += a0 * v;
                acc[1][c] += a1 * v;
            }
        }
        __syncthreads();
    }

    #pragma unroll
    for (int u = 0; u < 2; u++) {
        int ig = i0 + ip + 32*u;
        #pragma unroll
        for (int c = 0; c < 5; c++) {
            int col = q*5 + c;
            if (col < 16) g_o  [((size_t)b * NN + ig) * HC   + h * NC + col]      = acc[u][c];
            else          g_opt[((size_t)b * NN + ig) * HPV3 + h * 24 + (col-16)] = acc[u][c];
        }
    }
}

// ================= K5: final features + output GEMV, 4 rows/block =================
#define K5R 4
__global__ void k5_out(const float* __restrict__ rot,
                       const float* __restrict__ trans,
                       const float* __restrict__ Wout,
                       const float* __restrict__ bout,
                       float* __restrict__ sout)
{
    __shared__ float feats[K5R*576];
    int bi0 = blockIdx.x * K5R;
    int tid = threadIdx.x;

    for (int idx = tid; idx < K5R*HC; idx += 384) {
        int r = idx / HC, c = idx - r*HC;
        feats[r*576 + c] = g_o[(size_t)(bi0+r) * HC + c];
    }
    for (int idx = tid; idx < K5R*96; idx += 384) {
        int r = idx / 96, kidx = idx - r*96;
        int bi = bi0 + r;
        const float* rp = rot + (size_t)bi * 9;
        const float* tp = trans + (size_t)bi * 3;
        float oy0 = g_opt[(size_t)bi * HPV3 + kidx*3+0] - tp[0] * 0.1f;
        float oy1 = g_opt[(size_t)bi * HPV3 + kidx*3+1] - tp[1] * 0.1f;
        float oy2 = g_opt[(size_t)bi * HPV3 + kidx*3+2] - tp[2] * 0.1f;
        float l0 = rp[0]*oy0 + rp[3]*oy1 + rp[6]*oy2;
        float l1 = rp[1]*oy0 + rp[4]*oy1 + rp[7]*oy2;
        float l2 = rp[2]*oy0 + rp[5]*oy1 + rp[8]*oy2;
        feats[r*576 + 192 + kidx] = l0;
        feats[r*576 + 288 + kidx] = l1;
        feats[r*576 + 384 + kidx] = l2;
        feats[r*576 + 480 + kidx] = sqrtf(l0*l0 + l1*l1 + l2*l2 + 1e-8f);
    }
    __syncthreads();

    int cs = tid;  // blockDim = 384
    float acc[K5R];
    float bb = bout[cs];
    #pragma unroll
    for (int r = 0; r < K5R; r++) acc[r] = bb;
    for (int f0 = 0; f0 < 576; f0 += 8) {
        float w[8];
        #pragma unroll
        for (int u = 0; u < 8; u++) w[u] = Wout[(size_t)(f0+u) * CSD + cs];
        #pragma unroll
        for (int u = 0; u < 8; u++) {
            #pragma unroll
            for (int r = 0; r < K5R; r++) acc[r] += feats[r*576 + f0 + u] * w[u];
        }
    }
    #pragma unroll
    for (int r = 0; r < K5R; r++)
        sout[(size_t)(bi0+r) * CSD + cs] = acc[r];
}

// ================= launch =================
extern "C" void kernel_launch(void* const* d_in, const int* in_sizes, int n_in,
                              void* d_out, int out_size)
{
    const float* s        = (const float*)d_in[0];
    const float* rot      = (const float*)d_in[1];
    const float* trans    = (const float*)d_in[2];
    const float* mask     = (const float*)d_in[3];
    const float* Wq       = (const float*)d_in[4];
    const float* bq       = (const float*)d_in[5];
    const float* Wkv      = (const float*)d_in[6];
    const float* bkv      = (const float*)d_in[7];
    const float* head_w   = (const float*)d_in[8];
    const float* ln_g     = (const float*)d_in[9];
    const float* ln_b     = (const float*)d_in[10];
    const float* Wpq      = (const float*)d_in[11];
    const float* bpq      = (const float*)d_in[12];
    const float* Wpv      = (const float*)d_in[13];
    const float* bpv      = (const float*)d_in[14];
    const float* Wvl      = (const float*)d_in[15];
    const float* gbf_mean = (const float*)d_in[16];
    const float* gbf_std  = (const float*)d_in[17];
    const float* Wg       = (const float*)d_in[18];
    const float* bg       = (const float*)d_in[19];
    const float* W1       = (const float*)d_in[20];
    const float* b1       = (const float*)d_in[21];
    const float* W2       = (const float*)d_in[22];
    const float* b2       = (const float*)d_in[23];
    const float* Wkvp     = (const float*)d_in[24];
    const float* bkvp     = (const float*)d_in[25];
    const float* Wout     = (const float*)d_in[26];
    const float* bout     = (const float*)d_in[27];

    float* out = (float*)d_out;
    float* sout_part = out;                              // (B,N,CS)
    float* g_part = out + (size_t)NB * NN * CSD;         // (B,N,N,G)

    cudaFuncSetAttribute((const void*)k2_pair,
                         cudaFuncAttributeMaxDynamicSharedMemorySize, SMEM2_BYTES);

    k1_project<<<NB * NN / K1R, 256>>>(s, rot, trans, Wq, bq, Wkv, bkv,
                                       ln_g, ln_b, Wpq, bpq, Wpv, bpv, Wkvp, bkvp);
    k2_pair<<<NB * NN, 256, SMEM2_BYTES>>>(rot, trans, mask, head_w, Wvl,
                                           gbf_mean, gbf_std, Wg, bg, W1, b1,
                                           W2, b2, g_part);
    k3_softmax<<<NB * NH * NN, 256>>>();
    k4_attn<<<NB * NH * (NN/64), 256>>>();
    k5_out<<<NB * NN / K5R, 384>>>(rot, trans, Wout, bout, sout_part);
}

// round 14
// speedup vs baseline: 1.5133x; 1.2352x over previous
#include <cuda_runtime.h>
#include <cuda_bf16.h>
#include <math.h>
#include <stdint.h>

// Problem dims
#define NB 2
#define NN 512
#define CSD 384
#define NH 12
#define NC 16
#define NP 8
#define NPV 8
#define NK 16
#define NG 64
#define HC (NH*NC)          // 192
#define HPV3 (NH*NPV*3)     // 288

// ---------------- scratch (device globals) -------------
__device__ __align__(16) float g_q   [NB*NN*HC];
__device__ __align__(16) float g_k   [NB*NN*HC];
__device__ __align__(16) float g_v   [NB*NN*HC];
__device__ __align__(16) float g_qpts[NB*NN*NP*3];
__device__ __align__(16) float g_vpts[NB*NN*NP*3];
__device__ __align__(16) float g_vg  [NB*NN*HPV3];
__device__ __align__(16) float g_logits[(size_t)NB*NH*NN*NN];
__device__ __align__(16) float g_o   [NB*NN*HC];
__device__ __align__(16) float g_opt [NB*NN*HPV3];

// bf16 HMMA m16n8k16 (baseline PTX, compiles for compute_103)
__device__ __forceinline__ void mma_bf16(float* c, const uint32_t* a, uint32_t b0, uint32_t b1) {
    asm volatile("mma.sync.aligned.m16n8k16.row.col.f32.bf16.bf16.f32 "
        "{%0,%1,%2,%3}, {%4,%5,%6,%7}, {%8,%9}, {%0,%1,%2,%3};"
        : "+f"(c[0]), "+f"(c[1]), "+f"(c[2]), "+f"(c[3])
        : "r"(a[0]), "r"(a[1]), "r"(a[2]), "r"(a[3]), "r"(b0), "r"(b1));
}

// ================= K1: per-row projections, 8 rows per block =================
#define K1R 8
__global__ void k1_project(const float* __restrict__ s,
                           const float* __restrict__ rot,
                           const float* __restrict__ trans,
                           const float* __restrict__ Wq,  const float* __restrict__ bq,
                           const float* __restrict__ Wkv, const float* __restrict__ bkv,
                           const float* __restrict__ ln_g,const float* __restrict__ ln_b,
                           const float* __restrict__ Wpq, const float* __restrict__ bpq,
                           const float* __restrict__ Wpv, const float* __restrict__ bpv,
                           const float* __restrict__ Wkvp,const float* __restrict__ bkvp)
{
    __shared__ float ssh [K1R*CSD];
    __shared__ float snsh[K1R*CSD];
    __shared__ float kvpsh[K1R*HPV3];

    int bn0 = blockIdx.x * K1R;
    int tid = threadIdx.x;
    int wid = tid >> 5, lane = tid & 31;

    for (int idx = tid; idx < K1R*CSD; idx += blockDim.x)
        ssh[idx] = s[(size_t)bn0 * CSD + idx];
    __syncthreads();

    {
        int r = wid;
        const float* row = ssh + r * CSD;
        float lsum = 0.f;
        for (int i = lane; i < CSD; i += 32) lsum += row[i];
        #pragma unroll
        for (int o = 16; o > 0; o >>= 1) lsum += __shfl_xor_sync(0xffffffffu, lsum, o);
        float mean = lsum * (1.0f / CSD);
        float lvar = 0.f;
        for (int i = lane; i < CSD; i += 32) { float d = row[i] - mean; lvar += d * d; }
        #pragma unroll
        for (int o = 16; o > 0; o >>= 1) lvar += __shfl_xor_sync(0xffffffffu, lvar, o);
        float inv = rsqrtf(lvar * (1.0f / CSD) + 1e-5f);
        for (int i = lane; i < CSD; i += 32)
            snsh[r * CSD + i] = (row[i] - mean) * inv * ln_g[i] + ln_b[i];
    }
    __syncthreads();

    for (int col = tid; col < 912; col += blockDim.x) {
        float acc[K1R];
        if (col < HC) {
            #pragma unroll
            for (int r = 0; r < K1R; r++) acc[r] = bq[col];
            for (int cs = 0; cs < CSD; cs++) {
                float w = Wq[(size_t)cs * HC + col];
                #pragma unroll
                for (int r = 0; r < K1R; r++) acc[r] += ssh[r*CSD+cs] * w;
            }
            #pragma unroll
            for (int r = 0; r < K1R; r++) g_q[(size_t)(bn0+r) * HC + col] = acc[r];
        } else if (col < 3*HC) {
            int j2 = col - HC;
            #pragma unroll
            for (int r = 0; r < K1R; r++) acc[r] = bkv[j2];
            for (int cs = 0; cs < CSD; cs++) {
                float w = Wkv[(size_t)cs * (2*HC) + j2];
                #pragma unroll
                for (int r = 0; r < K1R; r++) acc[r] += ssh[r*CSD+cs] * w;
            }
            int h = j2 >> 5, rr = j2 & 31;
            #pragma unroll
            for (int r = 0; r < K1R; r++) {
                if (rr < NC) g_k[(size_t)(bn0+r) * HC + h * NC + rr] = acc[r];
                else         g_v[(size_t)(bn0+r) * HC + h * NC + (rr - NC)] = acc[r];
            }
        } else if (col < 600) {
            int c2 = col - 576;
            #pragma unroll
            for (int r = 0; r < K1R; r++) acc[r] = bpq[c2];
            for (int cs = 0; cs < CSD; cs++) {
                float w = Wpq[(size_t)cs * (NP*3) + c2];
                #pragma unroll
                for (int r = 0; r < K1R; r++) acc[r] += snsh[r*CSD+cs] * w;
            }
            #pragma unroll
            for (int r = 0; r < K1R; r++) g_qpts[(size_t)(bn0+r) * (NP*3) + c2] = acc[r];
        } else if (col < 624) {
            int c2 = col - 600;
            #pragma unroll
            for (int r = 0; r < K1R; r++) acc[r] = bpv[c2];
            for (int cs = 0; cs < CSD; cs++) {
                float w = Wpv[(size_t)cs * (NP*3) + c2];
                #pragma unroll
                for (int r = 0; r < K1R; r++) acc[r] += snsh[r*CSD+cs] * w;
            }
            #pragma unroll
            for (int r = 0; r < K1R; r++) g_vpts[(size_t)(bn0+r) * (NP*3) + c2] = acc[r];
        } else {
            int c2 = col - 624;
            #pragma unroll
            for (int r = 0; r < K1R; r++) acc[r] = bkvp[c2];
            for (int cs = 0; cs < CSD; cs++) {
                float w = Wkvp[(size_t)cs * HPV3 + c2];
                #pragma unroll
                for (int r = 0; r < K1R; r++) acc[r] += ssh[r*CSD+cs] * w;
            }
            #pragma unroll
            for (int r = 0; r < K1R; r++) kvpsh[r*HPV3 + c2] = acc[r];
        }
    }
    __syncthreads();

    for (int t = tid; t < K1R*HPV3; t += blockDim.x) {
        int r = t / HPV3, e = t - r*HPV3;
        int kidx = e / 3, x = e % 3;
        int bn = bn0 + r;
        const float* rp = rot + (size_t)bn * 9;
        const float* tp = trans + (size_t)bn * 3;
        float vv = tp[x] * 0.1f;
        #pragma unroll
        for (int y = 0; y < 3; y++) vv += rp[x * 3 + y] * kvpsh[r*HPV3 + kidx * 3 + y];
        g_vg[(size_t)bn * HPV3 + e] = vv;
    }
}

// ========== K2: pair stage — bf16 HMMA (hi/lo split) for stages D & E =========
// byte offsets into dynamic smem
#define SM_WGHI  0                       // WgT hi  [64n][136k] bf16 = 17408
#define SM_WGLO  17408                   // WgT lo
#define SM_W1HI  34816                   // W1T hi  [64n][72k]  bf16 = 9216
#define SM_W1LO  44032                   // W1T lo
#define SM_GAHI  53248                   // gauss hi [64j][136k] bf16 = 17408
#define SM_GALO  70656                   // gauss lo
#define SM_GSHI  88064                   // g hi    [64j][72k] bf16 = 9216
#define SM_GSLO  97280                   // g lo
#define SM_FLT   106496                  // float region
// float region offsets (floats)
#define F_W2    0       // 768
#define F_BG    768     // 64
#define F_B1    832     // 64
#define F_B2    896     // 12
#define F_HW    908     // 12
#define F_ROTI  920     // 9
#define F_TI    929     // 3
#define F_MASK  932     // 1 (pad 936)
#define F_QPTS  936     // 24
#define F_QVL   960     // 24
#define F_WVL   984     // 128
#define F_MEAN  1112    // 16
#define F_ISTD  1128    // 16
#define F_QI    1144    // 192 -> 1336
#define F_VLOC  1336    // 64*25 -> 2936
#define F_VLEN  2936    // 64*8  -> 3448
#define F_H1    3448    // 64*68 -> 7800
#define F_TOTAL 7800
#define SMEM2_BYTES (SM_FLT + F_TOTAL*4)   // 137,696 B
#define JT 64

__device__ __forceinline__ void split_store(char* sm, int hi_base, int lo_base,
                                            int byte_off, float v0, float v1) {
    __nv_bfloat16 h0 = __float2bfloat16(v0), h1 = __float2bfloat16(v1);
    __nv_bfloat16 l0 = __float2bfloat16(v0 - __bfloat162float(h0));
    __nv_bfloat16 l1 = __float2bfloat16(v1 - __bfloat162float(h1));
    *(__nv_bfloat162*)(sm + hi_base + byte_off) = __halves2bfloat162(h0, h1);
    *(__nv_bfloat162*)(sm + lo_base + byte_off) = __halves2bfloat162(l0, l1);
}

__global__ void __launch_bounds__(256)
k2_pair(const float* __restrict__ rot,
        const float* __restrict__ trans,
        const float* __restrict__ mask,
        const float* __restrict__ head_weights,
        const float* __restrict__ Wvl,
        const float* __restrict__ gbf_means,
        const float* __restrict__ gbf_stds,
        const float* __restrict__ Wg, const float* __restrict__ bg,
        const float* __restrict__ W1, const float* __restrict__ b1,
        const float* __restrict__ W2, const float* __restrict__ b2,
        float* __restrict__ g_out)
{
    extern __shared__ char sm[];
    float* fr = (float*)(sm + SM_FLT);
    int bi = blockIdx.x;
    int b = bi >> 9, i = bi & 511;
    int tid = threadIdx.x;

    // weights -> transposed bf16 hi/lo tiles
    for (int t = tid; t < 8192; t += 256) {          // Wg [128k][64n] -> WgT [n][k]
        int k = t >> 6, n = t & 63;
        float w = Wg[t];
        __nv_bfloat16 hi = __float2bfloat16(w);
        __nv_bfloat16 lo = __float2bfloat16(w - __bfloat162float(hi));
        int off = (n*136 + k) * 2;
        *(__nv_bfloat16*)(sm + SM_WGHI + off) = hi;
        *(__nv_bfloat16*)(sm + SM_WGLO + off) = lo;
    }
    for (int t = tid; t < 4096; t += 256) {          // W1 [64k][64n] -> W1T [n][k]
        int k = t >> 6, n = t & 63;
        float w = W1[t];
        __nv_bfloat16 hi = __float2bfloat16(w);
        __nv_bfloat16 lo = __float2bfloat16(w - __bfloat162float(hi));
        int off = (n*72 + k) * 2;
        *(__nv_bfloat16*)(sm + SM_W1HI + off) = hi;
        *(__nv_bfloat16*)(sm + SM_W1LO + off) = lo;
    }
    for (int t = tid; t < 768; t += 256) fr[F_W2 + t] = W2[t];
    if (tid < 128) fr[F_WVL + tid] = Wvl[tid];
    if (tid < NK) {
        fr[F_MEAN + tid] = gbf_means[tid];
        fr[F_ISTD + tid] = 1.0f / gbf_stds[tid];
    }
    if (tid < NG) { fr[F_BG + tid] = bg[tid]; fr[F_B1 + tid] = b1[tid]; }
    if (tid < NH) {
        fr[F_B2 + tid] = b2[tid];
        float x = head_weights[tid];
        float sp = logf(1.0f + expf(x));
        fr[F_HW + tid] = sp * (-0.11785113f);   // softplus * sqrt(1/18) * -0.5
    }
    if (tid < 9) fr[F_ROTI + tid] = rot[(size_t)bi * 9 + tid];
    if (tid < 3) fr[F_TI + tid] = trans[(size_t)bi * 3 + tid];
    if (tid < 24) fr[F_QPTS + tid] = g_qpts[(size_t)bi * 24 + tid];
    if (tid == 0) fr[F_MASK] = mask[bi];
    if (tid < HC) fr[F_QI + tid] = g_q[(size_t)bi * HC + tid];
    __syncthreads();

    if (tid < 24) {  // q-contribution of Wvl (j-independent)
        int o = tid / 3, x = tid % 3;
        float acc = 0.f;
        #pragma unroll
        for (int p = 0; p < NP; p++)
            acc += fr[F_WVL + o * 16 + 8 + p] * fr[F_QPTS + p * 3 + x];
        fr[F_QVL + tid] = acc;
    }
    __syncthreads();

    float ti0 = fr[F_TI + 0], ti1 = fr[F_TI + 1], ti2 = fr[F_TI + 2];
    float mi = fr[F_MASK];
    int wid = tid >> 5, lane = tid & 31;
    int jslab = wid >> 1;        // 0..3 -> j rows [jslab*16, +16)
    int nhalf = wid & 1;         // 0..1 -> n cols [nhalf*32, +32)
    int grp = lane >> 2, qd = lane & 3;

    for (int j0 = 0; j0 < NN; j0 += JT) {
        // ---- A: v_loc ----
        {
            int jj = tid >> 2, qq = tid & 3;
            int j = j0 + jj;
            const float* rj = rot + ((size_t)b * NN + j) * 9;
            const float* tj = trans + ((size_t)b * NN + j) * 3;
            float R[3][3], tr[3];
            #pragma unroll
            for (int x = 0; x < 3; x++) {
                float a0 = fr[F_ROTI + 0*3 + x];
                float a1 = fr[F_ROTI + 1*3 + x];
                float a2 = fr[F_ROTI + 2*3 + x];
                #pragma unroll
                for (int z = 0; z < 3; z++)
                    R[x][z] = a0 * rj[0*3+z] + a1 * rj[1*3+z] + a2 * rj[2*3+z];
                tr[x] = a0 * (tj[0] - ti0) + a1 * (tj[1] - ti1) + a2 * (tj[2] - ti2);
            }
            #pragma unroll
            for (int pp = 0; pp < 2; pp++) {
                int p = qq * 2 + pp;
                const float* vp = g_vpts + ((size_t)b * NN + j) * 24 + p * 3;
                float v0 = vp[0], v1 = vp[1], v2 = vp[2];
                #pragma unroll
                for (int x = 0; x < 3; x++)
                    fr[F_VLOC + jj*25 + p*3 + x] = R[x][0]*v0 + R[x][1]*v1 + R[x][2]*v2 + tr[x];
            }
        }
        __syncthreads();
        // ---- B: vec + vlen ----
        {
            int jj = tid >> 2, qq = tid & 3;
            const float* vl = fr + F_VLOC + jj*25;
            #pragma unroll
            for (int oo = 0; oo < 2; oo++) {
                int o = qq * 2 + oo;
                float vx = fr[F_QVL + o*3+0] + vl[o*3+0];
                float vy = fr[F_QVL + o*3+1] + vl[o*3+1];
                float vz = fr[F_QVL + o*3+2] + vl[o*3+2];
                #pragma unroll
                for (int p = 0; p < NP; p++) {
                    float w_ = fr[F_WVL + o * 16 + p];
                    vx += w_ * vl[p*3+0];
                    vy += w_ * vl[p*3+1];
                    vz += w_ * vl[p*3+2];
                }
                fr[F_VLEN + jj*8 + o] = sqrtf(vx*vx + vy*vy + vz*vz + 1e-8f);
            }
        }
        __syncthreads();
        // ---- C: gauss [64][128] -> bf16 hi/lo (pairs) ----
        #pragma unroll 4
        for (int it = 0; it < 16; it++) {
            int fp = tid + 256 * it;            // pair index 0..4095
            int jj = fp >> 6;
            int m0 = (fp & 63) << 1;
            int p = m0 >> 4;
            int kk = m0 & 15;
            float vl = fr[F_VLEN + jj*8 + p];
            float d0 = (vl - fr[F_MEAN + kk])   * fr[F_ISTD + kk];
            float d1 = (vl - fr[F_MEAN + kk+1]) * fr[F_ISTD + kk+1];
            float g0 = __expf(-0.5f * d0 * d0);
            float g1 = __expf(-0.5f * d1 * d1);
            split_store(sm, SM_GAHI, SM_GALO, (jj*136 + m0)*2, g0, g1);
        }
        __syncthreads();
        // ---- D: g[64][64] = gauss @ Wg (HMMA, 3-product split) ----
        {
            float acc[4][4];
            #pragma unroll
            for (int n8 = 0; n8 < 4; n8++)
                #pragma unroll
                for (int r = 0; r < 4; r++) acc[n8][r] = 0.f;
            #pragma unroll
            for (int k16 = 0; k16 < 8; k16++) {
                int abyte = ((jslab*16 + grp)*136 + k16*16 + qd*2) * 2;
                uint32_t ahi[4], alo[4];
                ahi[0] = *(const uint32_t*)(sm + SM_GAHI + abyte);
                ahi[1] = *(const uint32_t*)(sm + SM_GAHI + abyte + 8*136*2);
                ahi[2] = *(const uint32_t*)(sm + SM_GAHI + abyte + 16);
                ahi[3] = *(const uint32_t*)(sm + SM_GAHI + abyte + 8*136*2 + 16);
                alo[0] = *(const uint32_t*)(sm + SM_GALO + abyte);
                alo[1] = *(const uint32_t*)(sm + SM_GALO + abyte + 8*136*2);
                alo[2] = *(const uint32_t*)(sm + SM_GALO + abyte + 16);
                alo[3] = *(const uint32_t*)(sm + SM_GALO + abyte + 8*136*2 + 16);
                #pragma unroll
                for (int n8 = 0; n8 < 4; n8++) {
                    int bbyte = ((nhalf*32 + n8*8 + grp)*136 + k16*16 + qd*2) * 2;
                    uint32_t bh0 = *(const uint32_t*)(sm + SM_WGHI + bbyte);
                    uint32_t bh1 = *(const uint32_t*)(sm + SM_WGHI + bbyte + 16);
                    uint32_t bl0 = *(const uint32_t*)(sm + SM_WGLO + bbyte);
                    uint32_t bl1 = *(const uint32_t*)(sm + SM_WGLO + bbyte + 16);
                    mma_bf16(acc[n8], ahi, bh0, bh1);
                    mma_bf16(acc[n8], alo, bh0, bh1);
                    mma_bf16(acc[n8], ahi, bl0, bl1);
                }
            }
            // store: g_out (fp32) + gsm (bf16 hi/lo)
            int r0 = jslab*16 + grp, r1 = r0 + 8;
            #pragma unroll
            for (int n8 = 0; n8 < 4; n8++) {
                int c = nhalf*32 + n8*8 + qd*2;
                float bg0 = fr[F_BG + c], bg1 = fr[F_BG + c + 1];
                float v00 = acc[n8][0] + bg0, v01 = acc[n8][1] + bg1;
                float v10 = acc[n8][2] + bg0, v11 = acc[n8][3] + bg1;
                *(float2*)(g_out + ((size_t)bi*NN + j0 + r0)*NG + c) = make_float2(v00, v01);
                *(float2*)(g_out + ((size_t)bi*NN + j0 + r1)*NG + c) = make_float2(v10, v11);
                split_store(sm, SM_GSHI, SM_GSLO, (r0*72 + c)*2, v00, v01);
                split_store(sm, SM_GSHI, SM_GSLO, (r1*72 + c)*2, v10, v11);
            }
        }
        __syncthreads();
        // ---- E: h1[64][64] = relu(g @ W1 + b1) (HMMA, 3-product split) ----
        {
            float acc[4][4];
            #pragma unroll
            for (int n8 = 0; n8 < 4; n8++)
                #pragma unroll
                for (int r = 0; r < 4; r++) acc[n8][r] = 0.f;
            #pragma unroll
            for (int k16 = 0; k16 < 4; k16++) {
                int abyte = ((jslab*16 + grp)*72 + k16*16 + qd*2) * 2;
                uint32_t ahi[4], alo[4];
                ahi[0] = *(const uint32_t*)(sm + SM_GSHI + abyte);
                ahi[1] = *(const uint32_t*)(sm + SM_GSHI + abyte + 8*72*2);
                ahi[2] = *(const uint32_t*)(sm + SM_GSHI + abyte + 16);
                ahi[3] = *(const uint32_t*)(sm + SM_GSHI + abyte + 8*72*2 + 16);
                alo[0] = *(const uint32_t*)(sm + SM_GSLO + abyte);
                alo[1] = *(const uint32_t*)(sm + SM_GSLO + abyte + 8*72*2);
                alo[2] = *(const uint32_t*)(sm + SM_GSLO + abyte + 16);
                alo[3] = *(const uint32_t*)(sm + SM_GSLO + abyte + 8*72*2 + 16);
                #pragma unroll
                for (int n8 = 0; n8 < 4; n8++) {
                    int bbyte = ((nhalf*32 + n8*8 + grp)*72 + k16*16 + qd*2) * 2;
                    uint32_t bh0 = *(const uint32_t*)(sm + SM_W1HI + bbyte);
                    uint32_t bh1 = *(const uint32_t*)(sm + SM_W1HI + bbyte + 16);
                    uint32_t bl0 = *(const uint32_t*)(sm + SM_W1LO + bbyte);
                    uint32_t bl1 = *(const uint32_t*)(sm + SM_W1LO + bbyte + 16);
                    mma_bf16(acc[n8], ahi, bh0, bh1);
                    mma_bf16(acc[n8], alo, bh0, bh1);
                    mma_bf16(acc[n8], ahi, bl0, bl1);
                }
            }
            int r0 = jslab*16 + grp, r1 = r0 + 8;
            #pragma unroll
            for (int n8 = 0; n8 < 4; n8++) {
                int c = nhalf*32 + n8*8 + qd*2;
                float b10 = fr[F_B1 + c], b11 = fr[F_B1 + c + 1];
                *(float2*)(fr + F_H1 + r0*68 + c) =
                    make_float2(fmaxf(acc[n8][0] + b10, 0.f), fmaxf(acc[n8][1] + b11, 0.f));
                *(float2*)(fr + F_H1 + r1*68 + c) =
                    make_float2(fmaxf(acc[n8][2] + b10, 0.f), fmaxf(acc[n8][3] + b11, 0.f));
            }
        }
        __syncthreads();
        // ---- F: vfn + qk + dist -> logits ----
        for (int idx = tid; idx < JT * NH; idx += 256) {
            int jj = idx / NH, h = idx - jj * NH;
            int j = j0 + jj;
            float acc = fr[F_B2 + h];
            const float* h1 = fr + F_H1 + jj*68;
            #pragma unroll 8
            for (int m = 0; m < 64; m++)
                acc += h1[m] * fr[F_W2 + m * NH + h];
            const float4* kp = (const float4*)(g_k + ((size_t)b * NN + j) * HC + h * NC);
            const float4* qp = (const float4*)(fr + F_QI + h * NC);
            float qk = 0.f;
            #pragma unroll
            for (int c = 0; c < 4; c++) {
                float4 kk4 = kp[c], qq4 = qp[c];
                qk += qq4.x*kk4.x + qq4.y*kk4.y + qq4.z*kk4.z + qq4.w*kk4.w;
            }
            const float* tj = trans + ((size_t)b * NN + j) * 3;
            float d0 = (tj[0] - ti0) * 0.1f;
            float d1 = (tj[1] - ti1) * 0.1f;
            float d2 = (tj[2] - ti2) * 0.1f;
            float pd = d0*d0 + d1*d1 + d2*d2;
            float mj = mask[(size_t)b * NN + j];
            float logit = qk * 0.125f + acc * 0.5f + pd * fr[F_HW + h]
                        + 100000.0f * (mi * mj - 1.0f);
            g_logits[((((size_t)b * NH + h) * NN) + i) * NN + j] = logit;
        }
        __syncthreads();
    }
}

// ================= K3: softmax over last dim =================
__global__ void k3_softmax()
{
    __shared__ float red[32];
    size_t row = blockIdx.x;
    float* p = g_logits + row * NN;
    int tid = threadIdx.x;
    int lane = tid & 31, wid = tid >> 5;
    float v0 = p[tid], v1 = p[tid + 256];
    float mv = fmaxf(v0, v1);
    #pragma unroll
    for (int o = 16; o > 0; o >>= 1) mv = fmaxf(mv, __shfl_xor_sync(0xffffffffu, mv, o));
    if (lane == 0) red[wid] = mv;
    __syncthreads();
    float mx = (lane < 8) ? red[lane] : -1e30f;
    #pragma unroll
    for (int o = 4; o > 0; o >>= 1) mx = fmaxf(mx, __shfl_xor_sync(0xffffffffu, mx, o));
    mx = __shfl_sync(0xffffffffu, mx, 0);
    if (wid == 0 && lane == 0) red[0] = mx;
    __syncthreads();
    mx = red[0];
    float e0 = __expf(v0 - mx), e1 = __expf(v1 - mx);
    float sv = e0 + e1;
    #pragma unroll
    for (int o = 16; o > 0; o >>= 1) sv += __shfl_xor_sync(0xffffffffu, sv, o);
    __syncthreads();
    if (lane == 0) red[wid] = sv;
    __syncthreads();
    float sm = (lane < 8) ? red[lane] : 0.f;
    #pragma unroll
    for (int o = 4; o > 0; o >>= 1) sm += __shfl_xor_sync(0xffffffffu, sm, o);
    if (wid == 0 && lane == 0) red[0] = sm;
    __syncthreads();
    float inv = 1.0f / red[0];
    p[tid] = e0 * inv;
    p[tid + 256] = e1 * inv;
}

// ================= K4: attention-weighted sums, tiled GEMM =================
__global__ void k4_attn()
{
    __shared__ float a_sh[64*68];    // [i][j] pad 68
    __shared__ float v_sh[64*41];    // [j][col] pad 41

    int blk = blockIdx.x;
    int it = blk & 7;
    int h  = (blk >> 3) % 12;
    int b  = blk / (8 * 12);
    int i0 = it * 64;
    int tid = threadIdx.x;

    int q  = tid & 7;        // 5 cols each
    int ip = tid >> 3;       // i in {ip, ip+32}
    float acc[2][5];
    #pragma unroll
    for (int u = 0; u < 2; u++)
        #pragma unroll
        for (int c = 0; c < 5; c++) acc[u][c] = 0.f;

    const float* Arow = g_logits + (((size_t)b * NH + h) * NN + i0) * NN;

    for (int jt = 0; jt < NN; jt += 64) {
        for (int idx = tid; idx < 64*64; idx += 256) {
            int ii = idx >> 6, jj = idx & 63;
            a_sh[ii*68 + jj] = Arow[(size_t)ii * NN + jt + jj];
        }
        for (int idx = tid; idx < 64*40; idx += 256) {
            int jj = idx / 40, c = idx - jj*40;
            int j = jt + jj;
            float v;
            if (c < 16) v = g_v [((size_t)b * NN + j) * HC   + h * NC + c];
            else        v = g_vg[((size_t)b * NN + j) * HPV3 + h * 24 + (c - 16)];
            v_sh[jj*41 + c] = v;
        }
        __syncthreads();
        #pragma unroll 4
        for (int jj = 0; jj < 64; jj++) {
            float a0 = a_sh[ip*68 + jj];
            float a1 = a_sh[(ip+32)*68 + jj];
            const float* vp = v_sh + jj*41 + q*5;
            #pragma unroll
            for (int c = 0; c < 5; c++) {
                float v = vp[c];
                acc[0][c] += a0 * v;
                acc[1][c] += a1 * v;
            }
        }
        __syncthreads();
    }

    #pragma unroll
    for (int u = 0; u < 2; u++) {
        int ig = i0 + ip + 32*u;
        #pragma unroll
        for (int c = 0; c < 5; c++) {
            int col = q*5 + c;
            if (col < 16) g_o  [((size_t)b * NN + ig) * HC   + h * NC + col]      = acc[u][c];
            else          g_opt[((size_t)b * NN + ig) * HPV3 + h * 24 + (col-16)] = acc[u][c];
        }
    }
}

// ================= K5: final features + output GEMV, 4 rows/block =================
#define K5R 4
__global__ void k5_out(const float* __restrict__ rot,
                       const float* __restrict__ trans,
                       const float* __restrict__ Wout,
                       const float* __restrict__ bout,
                       float* __restrict__ sout)
{
    __shared__ float feats[K5R*576];
    int bi0 = blockIdx.x * K5R;
    int tid = threadIdx.x;

    for (int idx = tid; idx < K5R*HC; idx += 384) {
        int r = idx / HC, c = idx - r*HC;
        feats[r*576 + c] = g_o[(size_t)(bi0+r) * HC + c];
    }
    for (int idx = tid; idx < K5R*96; idx += 384) {
        int r = idx / 96, kidx = idx - r*96;
        int bi = bi0 + r;
        const float* rp = rot + (size_t)bi * 9;
        const float* tp = trans + (size_t)bi * 3;
        float oy0 = g_opt[(size_t)bi * HPV3 + kidx*3+0] - tp[0] * 0.1f;
        float oy1 = g_opt[(size_t)bi * HPV3 + kidx*3+1] - tp[1] * 0.1f;
        float oy2 = g_opt[(size_t)bi * HPV3 + kidx*3+2] - tp[2] * 0.1f;
        float l0 = rp[0]*oy0 + rp[3]*oy1 + rp[6]*oy2;
        float l1 = rp[1]*oy0 + rp[4]*oy1 + rp[7]*oy2;
        float l2 = rp[2]*oy0 + rp[5]*oy1 + rp[8]*oy2;
        feats[r*576 + 192 + kidx] = l0;
        feats[r*576 + 288 + kidx] = l1;
        feats[r*576 + 384 + kidx] = l2;
        feats[r*576 + 480 + kidx] = sqrtf(l0*l0 + l1*l1 + l2*l2 + 1e-8f);
    }
    __syncthreads();

    int cs = tid;  // blockDim = 384
    float acc[K5R];
    float bb = bout[cs];
    #pragma unroll
    for (int r = 0; r < K5R; r++) acc[r] = bb;
    for (int f0 = 0; f0 < 576; f0 += 8) {
        float w[8];
        #pragma unroll
        for (int u = 0; u < 8; u++) w[u] = Wout[(size_t)(f0+u) * CSD + cs];
        #pragma unroll
        for (int u = 0; u < 8; u++) {
            #pragma unroll
            for (int r = 0; r < K5R; r++) acc[r] += feats[r*576 + f0 + u] * w[u];
        }
    }
    #pragma unroll
    for (int r = 0; r < K5R; r++)
        sout[(size_t)(bi0+r) * CSD + cs] = acc[r];
}

// ================= launch =================
extern "C" void kernel_launch(void* const* d_in, const int* in_sizes, int n_in,
                              void* d_out, int out_size)
{
    const float* s        = (const float*)d_in[0];
    const float* rot      = (const float*)d_in[1];
    const float* trans    = (const float*)d_in[2];
    const float* mask     = (const float*)d_in[3];
    const float* Wq       = (const float*)d_in[4];
    const float* bq       = (const float*)d_in[5];
    const float* Wkv      = (const float*)d_in[6];
    const float* bkv      = (const float*)d_in[7];
    const float* head_w   = (const float*)d_in[8];
    const float* ln_g     = (const float*)d_in[9];
    const float* ln_b     = (const float*)d_in[10];
    const float* Wpq      = (const float*)d_in[11];
    const float* bpq      = (const float*)d_in[12];
    const float* Wpv      = (const float*)d_in[13];
    const float* bpv      = (const float*)d_in[14];
    const float* Wvl      = (const float*)d_in[15];
    const float* gbf_mean = (const float*)d_in[16];
    const float* gbf_std  = (const float*)d_in[17];
    const float* Wg       = (const float*)d_in[18];
    const float* bg       = (const float*)d_in[19];
    const float* W1       = (const float*)d_in[20];
    const float* b1       = (const float*)d_in[21];
    const float* W2       = (const float*)d_in[22];
    const float* b2       = (const float*)d_in[23];
    const float* Wkvp     = (const float*)d_in[24];
    const float* bkvp     = (const float*)d_in[25];
    const float* Wout     = (const float*)d_in[26];
    const float* bout     = (const float*)d_in[27];

    float* out = (float*)d_out;
    float* sout_part = out;                              // (B,N,CS)
    float* g_part = out + (size_t)NB * NN * CSD;         // (B,N,N,G)

    cudaFuncSetAttribute((const void*)k2_pair,
                         cudaFuncAttributeMaxDynamicSharedMemorySize, SMEM2_BYTES);

    k1_project<<<NB * NN / K1R, 256>>>(s, rot, trans, Wq, bq, Wkv, bkv,
                                       ln_g, ln_b, Wpq, bpq, Wpv, bpv, Wkvp, bkvp);
    k2_pair<<<NB * NN, 256, SMEM2_BYTES>>>(rot, trans, mask, head_w, Wvl,
                                           gbf_mean, gbf_std, Wg, bg, W1, b1,
                                           W2, b2, g_part);
    k3_softmax<<<NB * NH * NN, 256>>>();
    k4_attn<<<NB * NH * (NN/64), 256>>>();
    k5_out<<<NB * NN / K5R, 384>>>(rot, trans, Wout, bout, sout_part);
}